// round 12
// baseline (speedup 1.0000x reference)
#include <cuda_runtime.h>
#include <cuda_bf16.h>
#include <cuda_fp16.h>
#include <cstdint>
#include <math.h>

#define B_  2
#define T_  2048
#define C_  768
#define NH  12
#define HD  64
#define QKV_STRIDE (3*C_)
#define M_  (B_*T_)          // 4096

// ---------------------------------------------------------------------------
// Scratch (allocation-free rule: __device__ globals).
// ---------------------------------------------------------------------------
__device__ __half g_xh [(size_t)M_*C_];     // x hi (fp16)
__device__ __half g_xl [(size_t)M_*C_];     // x lo (fp16 residual)
__device__ __half g_wa [(size_t)3*C_*C_];   // W_attn fp16
__device__ __half g_wp [(size_t)C_*C_];     // W_proj fp16
__device__ __half g_qf [(size_t)M_*3*C_];   // qkv fp16
__device__ __half g_ah [(size_t)M_*C_];     // attn out hi (fp16)
__device__ __half g_al [(size_t)M_*C_];     // attn out lo (fp16)

// ---------------------------------------------------------------------------
// helpers
// ---------------------------------------------------------------------------
__device__ __forceinline__ uint32_t smem_u32(const void* p) {
    uint32_t a;
    asm("{ .reg .u64 t; cvta.to.shared.u64 t, %1; cvt.u32.u64 %0, t; }"
        : "=r"(a) : "l"(p));
    return a;
}
__device__ __forceinline__ void cp16(uint32_t dst, const void* src) {
    asm volatile("cp.async.cg.shared.global [%0], [%1], 16;" :: "r"(dst), "l"(src));
}
#define CP_COMMIT() asm volatile("cp.async.commit_group;" ::: "memory")
#define CP_WAIT0()  asm volatile("cp.async.wait_group 0;" ::: "memory")
#define CP_WAIT1()  asm volatile("cp.async.wait_group 1;" ::: "memory")

__device__ __forceinline__ void ldm_x4(uint32_t* r, uint32_t addr) {
    asm volatile("ldmatrix.sync.aligned.m8n8.x4.shared.b16 {%0,%1,%2,%3}, [%4];"
                 : "=r"(r[0]), "=r"(r[1]), "=r"(r[2]), "=r"(r[3]) : "r"(addr));
}
__device__ __forceinline__ void ldm_x4_t(uint32_t* r, uint32_t addr) {
    asm volatile("ldmatrix.sync.aligned.m8n8.x4.trans.shared.b16 {%0,%1,%2,%3}, [%4];"
                 : "=r"(r[0]), "=r"(r[1]), "=r"(r[2]), "=r"(r[3]) : "r"(addr));
}
__device__ __forceinline__ void mma_f16(float* c, const uint32_t* a, const uint32_t* b) {
    asm volatile(
        "mma.sync.aligned.m16n8k16.row.col.f32.f16.f16.f32 "
        "{%0,%1,%2,%3}, {%4,%5,%6,%7}, {%8,%9}, {%0,%1,%2,%3};"
        : "+f"(c[0]), "+f"(c[1]), "+f"(c[2]), "+f"(c[3])
        : "r"(a[0]), "r"(a[1]), "r"(a[2]), "r"(a[3]), "r"(b[0]), "r"(b[1]));
}
__device__ __forceinline__ uint32_t pack_h2(float a, float b) {
    __half2 v = __floats2half2_rn(a, b);
    return *(uint32_t*)&v;
}

// ---------------------------------------------------------------------------
// conversion kernels
// ---------------------------------------------------------------------------
__global__ __launch_bounds__(256) void split_f32_h(const float* __restrict__ src,
                                                   __half* __restrict__ h,
                                                   __half* __restrict__ l,
                                                   int n4) {
    int i = blockIdx.x * 256 + threadIdx.x;
    if (i >= n4) return;
    float4 v = *(const float4*)&src[(size_t)i * 4];
    float vv[4] = {v.x, v.y, v.z, v.w};
    __half hh[4], ll[4];
    #pragma unroll
    for (int j = 0; j < 4; j++) {
        hh[j] = __float2half_rn(vv[j]);
        ll[j] = __float2half_rn(vv[j] - __half2float(hh[j]));
    }
    *(uint2*)&h[(size_t)i * 4] = *(uint2*)hh;
    *(uint2*)&l[(size_t)i * 4] = *(uint2*)ll;
}

__global__ __launch_bounds__(256) void conv_f32_h(const float* __restrict__ src,
                                                  __half* __restrict__ h, int n4) {
    int i = blockIdx.x * 256 + threadIdx.x;
    if (i >= n4) return;
    float4 v = *(const float4*)&src[(size_t)i * 4];
    __half hh[4] = {__float2half_rn(v.x), __float2half_rn(v.y),
                    __float2half_rn(v.z), __float2half_rn(v.w)};
    *(uint2*)&h[(size_t)i * 4] = *(uint2*)hh;
}

// ---------------------------------------------------------------------------
// GEMM:  C[M,N] = (Ah+Al)[M,K] @ B[N,K]^T    (2-pass fp16; B single plane)
// 128x128 tile, BK=32, 256 threads (8 warps, 2x4; warp tile 64x32).
// 3-stage cp.async pipeline, 90 KB smem -> 2 CTAs/SM (barrier overlap).
// OUT_MODE: 0 = fp32, 2 = fp16 single plane.
// ---------------------------------------------------------------------------
#define G_ROW   80
#define G_AH    0
#define G_AL    10240
#define G_B     20480
#define G_STAGE 30720
#define G_SMEM  (3*G_STAGE)

__device__ __forceinline__ void gemm_issue(uint32_t sb,
                                           const __half* Ah, const __half* Al,
                                           const __half* Bf,
                                           int row0, int col0, int k0, int K, int t) {
    // A planes: 128 rows x 4 segs = 512 slots -> 2 per thread per plane
    #pragma unroll
    for (int p = 0; p < 2; p++) {
        int id = t + p * 256;
        int r = id >> 2, s = id & 3;
        uint32_t d = sb + r * G_ROW + s * 16;
        size_t ga = (size_t)(row0 + r) * K + k0 + s * 8;
        cp16(d + G_AH, Ah + ga);
        cp16(d + G_AL, Al + ga);
    }
    // B plane: 128 rows x 4 segs = 512 slots -> 2 per thread
    #pragma unroll
    for (int p = 0; p < 2; p++) {
        int id = t + p * 256;
        int r = id >> 2, s = id & 3;
        uint32_t d = sb + r * G_ROW + s * 16;
        size_t gb = (size_t)(col0 + r) * K + k0 + s * 8;
        cp16(d + G_B, Bf + gb);
    }
}

template<int OUT_MODE>
__global__ __launch_bounds__(256, 2) void gemm_f16(const __half* __restrict__ Ah,
                                                   const __half* __restrict__ Al,
                                                   const __half* __restrict__ Bf,
                                                   float* __restrict__ Cf,
                                                   __half* __restrict__ Ch16,
                                                   int M, int N, int K) {
    extern __shared__ __align__(16) char dyn[];
    const uint32_t sbase = smem_u32(dyn);

    const int t    = threadIdx.x;
    const int lane = t & 31;
    const int wid  = t >> 5;
    const int wm   = (wid >> 2) * 64;   // 2 M groups of 64
    const int wn   = (wid & 3) * 32;    // 4 N groups of 32
    const int row0 = blockIdx.y * 128;
    const int col0 = blockIdx.x * 128;
    const int lrow = lane & 15;
    const int lkof = (lane >> 4) << 3;

    float acc[4][4][4];
    #pragma unroll
    for (int i = 0; i < 4; i++)
        #pragma unroll
        for (int j = 0; j < 4; j++)
            #pragma unroll
            for (int q = 0; q < 4; q++) acc[i][j][q] = 0.f;

    const int nchunk = K / 32;   // 24

    gemm_issue(sbase, Ah, Al, Bf, row0, col0, 0, K, t);
    CP_COMMIT();
    gemm_issue(sbase + G_STAGE, Ah, Al, Bf, row0, col0, 32, K, t);
    CP_COMMIT();

    int stage = 0;
    for (int ch = 0; ch < nchunk; ++ch) {
        if (ch + 1 < nchunk) { CP_WAIT1(); } else { CP_WAIT0(); }
        __syncthreads();
        if (ch + 2 < nchunk) {
            int ns = stage + 2; if (ns >= 3) ns -= 3;
            gemm_issue(sbase + ns * G_STAGE, Ah, Al, Bf,
                       row0, col0, (ch + 2) * 32, K, t);
            CP_COMMIT();
        }
        const uint32_t sb = sbase + stage * G_STAGE;
        if (++stage == 3) stage = 0;

        #pragma unroll
        for (int ks = 0; ks < 2; ks++) {
            const int kb = ks * 16 + lkof;

            uint32_t ah[4][4], al[4][4];
            #pragma unroll
            for (int mf = 0; mf < 4; mf++) {
                uint32_t aoff = (uint32_t)((wm + mf * 16 + lrow) * G_ROW + kb * 2);
                ldm_x4(ah[mf], sb + G_AH + aoff);
                ldm_x4(al[mf], sb + G_AL + aoff);
            }
            #pragma unroll
            for (int nn = 0; nn < 2; nn++) {
                uint32_t boff = (uint32_t)((wn + nn * 16 + lrow) * G_ROW + kb * 2);
                uint32_t rb[4];
                ldm_x4(rb, sb + G_B + boff);
                uint32_t b0[2] = {rb[0], rb[2]};
                uint32_t b1[2] = {rb[1], rb[3]};
                #pragma unroll
                for (int mf = 0; mf < 4; mf++) {
                    mma_f16(acc[mf][2*nn],   ah[mf], b0);
                    mma_f16(acc[mf][2*nn],   al[mf], b0);
                    mma_f16(acc[mf][2*nn+1], ah[mf], b1);
                    mma_f16(acc[mf][2*nn+1], al[mf], b1);
                }
            }
        }
        // no bottom barrier: this stage is rewritten only after the next
        // iteration's top barrier (all warps done reading it).
    }

    #pragma unroll
    for (int mf = 0; mf < 4; mf++) {
        const int row = row0 + wm + mf * 16 + (lane >> 2);
        #pragma unroll
        for (int nf = 0; nf < 4; nf++) {
            const int col = col0 + wn + nf * 8 + (lane & 3) * 2;
            if (OUT_MODE == 2) {
                #pragma unroll
                for (int half_ = 0; half_ < 2; half_++) {
                    const size_t o = (size_t)(row + half_ * 8) * N + col;
                    __half2 hv = __floats2half2_rn(acc[mf][nf][2*half_],
                                                   acc[mf][nf][2*half_ + 1]);
                    *(__half2*)&Ch16[o] = hv;
                }
            } else {
                *(float2*)&Cf[(size_t)row * N + col] =
                    make_float2(acc[mf][nf][0], acc[mf][nf][1]);
                *(float2*)&Cf[(size_t)(row + 8) * N + col] =
                    make_float2(acc[mf][nf][2], acc[mf][nf][3]);
            }
        }
    }
}

// ---------------------------------------------------------------------------
// Flash attention, causal, single-pass fp16 mma, cp.async double-buffered K/V.
// CTA: 128 queries x (head,batch); 8 warps; 16 q-rows/warp; register softmax.
// Writes fp16 hi/lo planes (exact) for the proj GEMM.
// ---------------------------------------------------------------------------
#define A_ROW   144
#define A_K     0
#define A_V     9216
#define A_STAGE 18432
#define A_SMEM  (2*A_STAGE)

__device__ __forceinline__ void attn_issue(uint32_t sb, const __half* qf,
                                           size_t base, int k0, int kcol, int vcol, int t) {
    #pragma unroll
    for (int p = 0; p < 2; p++) {
        int id = t + p * 256;
        int r = id >> 3, s = id & 7;
        size_t gk = base + (size_t)(k0 + r) * QKV_STRIDE + kcol + s * 8;
        size_t gv = base + (size_t)(k0 + r) * QKV_STRIDE + vcol + s * 8;
        uint32_t d = sb + r * A_ROW + s * 16;
        cp16(d + A_K, qf + gk);
        cp16(d + A_V, qf + gv);
    }
}

__global__ __launch_bounds__(256) void attn_mma(const __half* __restrict__ qf16,
                                                __half* __restrict__ oh,
                                                __half* __restrict__ ol) {
    extern __shared__ __align__(16) char dyn[];
    const uint32_t sbase = smem_u32(dyn);

    const int t    = threadIdx.x;
    const int lane = t & 31;
    const int w    = t >> 5;
    const int q0   = (gridDim.x - 1 - blockIdx.x) * 128;   // heavy blocks first
    const int h    = blockIdx.y;
    const int b    = blockIdx.z;
    const size_t base = (size_t)b * T_ * QKV_STRIDE;
    const int qcol = h * HD;
    const int kcol = C_ + h * HD;
    const int vcol = 2 * C_ + h * HD;
    const int lrow = lane & 15;
    const int lkof = (lane >> 4) << 3;

    // ---- stage Q (128x64 fp16) into stage 0, frag to regs ----
    #pragma unroll
    for (int p = 0; p < 4; p++) {
        int id = t + p * 256;
        int r = id >> 3, s = id & 7;
        size_t g = base + (size_t)(q0 + r) * QKV_STRIDE + qcol + s * 8;
        uint32_t d = sbase + (r < 64 ? A_K + r * A_ROW : A_V + (r - 64) * A_ROW) + s * 16;
        cp16(d, qf16 + g);
    }
    CP_COMMIT();
    CP_WAIT0();
    __syncthreads();

    uint32_t qf[4][4];
    {
        const uint32_t bq = sbase + (w < 4 ? A_K : A_V);
        const uint32_t rofs = (uint32_t)(((w & 3) * 16 + lrow) * A_ROW);
        #pragma unroll
        for (int ks = 0; ks < 4; ks++) {
            uint32_t co = (uint32_t)((ks * 16 + lkof) * 2);
            ldm_x4(qf[ks], bq + rofs + co);
        }
    }
    __syncthreads();

    float mA = -1e30f, mB = -1e30f, lA = 0.f, lB = 0.f;
    float oacc[8][4];
    #pragma unroll
    for (int i = 0; i < 8; i++)
        #pragma unroll
        for (int j = 0; j < 4; j++) oacc[i][j] = 0.f;

    const int rowA = q0 + w * 16 + (lane >> 2);
    const int rowmax = q0 + w * 16 + 15;
    const int ntiles = q0 / 64 + 2;

    attn_issue(sbase, qf16, base, 0, kcol, vcol, t);
    CP_COMMIT();

    for (int kt = 0; kt < ntiles; kt++) {
        const int k0 = kt * 64;
        CP_WAIT0();
        __syncthreads();
        if (kt + 1 < ntiles) {
            attn_issue(sbase + ((kt + 1) & 1) * A_STAGE, qf16, base,
                       (kt + 1) * 64, kcol, vcol, t);
            CP_COMMIT();
        }
        const uint32_t sb = sbase + (kt & 1) * A_STAGE;

        if (k0 <= rowmax) {
            // ---- S = Q K^T ----
            float sacc[8][4];
            #pragma unroll
            for (int i = 0; i < 8; i++)
                #pragma unroll
                for (int j = 0; j < 4; j++) sacc[i][j] = 0.f;

            #pragma unroll
            for (int ks = 0; ks < 4; ks++) {
                const uint32_t co = (uint32_t)((ks * 16 + lkof) * 2);
                #pragma unroll
                for (int nn = 0; nn < 4; nn++) {
                    uint32_t ro = (uint32_t)((nn * 16 + lrow) * A_ROW);
                    uint32_t rh[4];
                    ldm_x4(rh, sb + A_K + ro + co);
                    uint32_t k0f[2] = {rh[0], rh[2]};
                    uint32_t k1f[2] = {rh[1], rh[3]};
                    mma_f16(sacc[2*nn],   qf[ks], k0f);
                    mma_f16(sacc[2*nn+1], qf[ks], k1f);
                }
            }

            // ---- scale + causal mask ----
            const bool need_mask = (k0 + 63 > q0 + w * 16);
            #pragma unroll
            for (int nf = 0; nf < 8; nf++) {
                #pragma unroll
                for (int j = 0; j < 4; j++) sacc[nf][j] *= 0.125f;
                if (need_mask) {
                    const int col = k0 + nf * 8 + (lane & 3) * 2;
                    if (col     > rowA)     sacc[nf][0] = -1e30f;
                    if (col + 1 > rowA)     sacc[nf][1] = -1e30f;
                    if (col     > rowA + 8) sacc[nf][2] = -1e30f;
                    if (col + 1 > rowA + 8) sacc[nf][3] = -1e30f;
                }
            }

            // ---- online softmax ----
            float tmA = -1e30f, tmB = -1e30f;
            #pragma unroll
            for (int nf = 0; nf < 8; nf++) {
                tmA = fmaxf(tmA, fmaxf(sacc[nf][0], sacc[nf][1]));
                tmB = fmaxf(tmB, fmaxf(sacc[nf][2], sacc[nf][3]));
            }
            tmA = fmaxf(tmA, __shfl_xor_sync(0xffffffffu, tmA, 1));
            tmA = fmaxf(tmA, __shfl_xor_sync(0xffffffffu, tmA, 2));
            tmB = fmaxf(tmB, __shfl_xor_sync(0xffffffffu, tmB, 1));
            tmB = fmaxf(tmB, __shfl_xor_sync(0xffffffffu, tmB, 2));

            const float mnA = fmaxf(mA, tmA);
            const float mnB = fmaxf(mB, tmB);
            const float aA = __expf(mA - mnA);
            const float aB = __expf(mB - mnB);

            float sumA = 0.f, sumB = 0.f;
            #pragma unroll
            for (int nf = 0; nf < 8; nf++) {
                sacc[nf][0] = __expf(sacc[nf][0] - mnA);
                sacc[nf][1] = __expf(sacc[nf][1] - mnA);
                sacc[nf][2] = __expf(sacc[nf][2] - mnB);
                sacc[nf][3] = __expf(sacc[nf][3] - mnB);
                sumA += sacc[nf][0] + sacc[nf][1];
                sumB += sacc[nf][2] + sacc[nf][3];
            }
            sumA += __shfl_xor_sync(0xffffffffu, sumA, 1);
            sumA += __shfl_xor_sync(0xffffffffu, sumA, 2);
            sumB += __shfl_xor_sync(0xffffffffu, sumB, 1);
            sumB += __shfl_xor_sync(0xffffffffu, sumB, 2);

            lA = lA * aA + sumA;  mA = mnA;
            lB = lB * aB + sumB;  mB = mnB;

            #pragma unroll
            for (int nf = 0; nf < 8; nf++) {
                oacc[nf][0] *= aA; oacc[nf][1] *= aA;
                oacc[nf][2] *= aB; oacc[nf][3] *= aB;
            }

            // ---- O += P V ----
            #pragma unroll
            for (int ks = 0; ks < 4; ks++) {
                uint32_t ph[4];
                ph[0] = pack_h2(sacc[2*ks][0],   sacc[2*ks][1]);
                ph[1] = pack_h2(sacc[2*ks][2],   sacc[2*ks][3]);
                ph[2] = pack_h2(sacc[2*ks+1][0], sacc[2*ks+1][1]);
                ph[3] = pack_h2(sacc[2*ks+1][2], sacc[2*ks+1][3]);

                const uint32_t krofs = (uint32_t)((ks * 16 + lrow) * A_ROW);
                #pragma unroll
                for (int nn = 0; nn < 4; nn++) {
                    uint32_t co = (uint32_t)((nn * 16 + lkof) * 2);
                    uint32_t vf[4];
                    ldm_x4_t(vf, sb + A_V + krofs + co);
                    uint32_t b0[2] = {vf[0], vf[1]};
                    uint32_t b1[2] = {vf[2], vf[3]};
                    mma_f16(oacc[2*nn],   ph, b0);
                    mma_f16(oacc[2*nn+1], ph, b1);
                }
            }
        }
    }

    // ---- epilogue: normalize, write fp16 hi/lo planes ----
    const float invA = 1.f / lA;
    const float invB = 1.f / lB;
    const size_t orowA = ((size_t)b * T_ + rowA) * C_ + h * HD;
    #pragma unroll
    for (int nf = 0; nf < 8; nf++) {
        const int col = nf * 8 + (lane & 3) * 2;
        #pragma unroll
        for (int half_ = 0; half_ < 2; half_++) {
            const size_t o = orowA + half_ * 8 * C_ + col;
            float v0 = oacc[nf][2*half_]     * (half_ ? invB : invA);
            float v1 = oacc[nf][2*half_ + 1] * (half_ ? invB : invA);
            __half h0 = __float2half_rn(v0);
            __half h1 = __float2half_rn(v1);
            __half2 hp; hp.x = h0; hp.y = h1;
            __half2 lp;
            lp.x = __float2half_rn(v0 - __half2float(h0));
            lp.y = __float2half_rn(v1 - __half2float(h1));
            *(__half2*)&oh[o] = hp;
            *(__half2*)&ol[o] = lp;
        }
    }
}

// ===========================================================================
extern "C" void kernel_launch(void* const* d_in, const int* in_sizes, int n_in,
                              void* d_out, int out_size) {
    const float* x      = (const float*)d_in[0];   // [B,T,C]
    const float* W_attn = (const float*)d_in[1];   // [3C,C]
    const float* W_proj = (const float*)d_in[2];   // [C,C]
    float* out = (float*)d_out;                    // [B,T,C]

    __half *xh, *xl, *wa, *wp, *qf, *ah, *al;
    cudaGetSymbolAddress((void**)&xh, g_xh); cudaGetSymbolAddress((void**)&xl, g_xl);
    cudaGetSymbolAddress((void**)&wa, g_wa); cudaGetSymbolAddress((void**)&wp, g_wp);
    cudaGetSymbolAddress((void**)&qf, g_qf);
    cudaGetSymbolAddress((void**)&ah, g_ah); cudaGetSymbolAddress((void**)&al, g_al);

    cudaFuncSetAttribute(gemm_f16<2>, cudaFuncAttributeMaxDynamicSharedMemorySize, G_SMEM);
    cudaFuncSetAttribute(gemm_f16<0>, cudaFuncAttributeMaxDynamicSharedMemorySize, G_SMEM);
    cudaFuncSetAttribute(attn_mma,    cudaFuncAttributeMaxDynamicSharedMemorySize, A_SMEM);

    // 0) conversions
    {
        int n4;
        n4 = M_ * C_ / 4;      split_f32_h<<<(n4 + 255) / 256, 256>>>(x, xh, xl, n4);
        n4 = 3 * C_ * C_ / 4;  conv_f32_h<<<(n4 + 255) / 256, 256>>>(W_attn, wa, n4);
        n4 = C_ * C_ / 4;      conv_f32_h<<<(n4 + 255) / 256, 256>>>(W_proj, wp, n4);
    }

    // 1) qkv = x @ W_attn^T  -> fp16   [4096 x 2304]
    gemm_f16<2><<<dim3((3*C_)/128, M_/128), 256, G_SMEM>>>(
        xh, xl, wa, nullptr, qf, M_, 3*C_, C_);

    // 2) causal attention (fp16) -> fp16 hi/lo planes
    attn_mma<<<dim3(T_/128, NH, B_), 256, A_SMEM>>>(qf, ah, al);

    // 3) out = attn @ W_proj^T -> fp32   [4096 x 768]
    gemm_f16<0><<<dim3(C_/128, M_/128), 256, G_SMEM>>>(
        ah, al, wp, out, nullptr, M_, C_, C_);
}

// round 13
// speedup vs baseline: 1.4042x; 1.4042x over previous
#include <cuda_runtime.h>
#include <cuda_bf16.h>
#include <cuda_fp16.h>
#include <cstdint>
#include <math.h>

#define B_  2
#define T_  2048
#define C_  768
#define NH  12
#define HD  64
#define QKV_STRIDE (3*C_)
#define M_  (B_*T_)          // 4096

// ---------------------------------------------------------------------------
// Scratch (allocation-free rule: __device__ globals). All fp16 single planes.
// ---------------------------------------------------------------------------
__device__ __half g_xf [(size_t)M_*C_];     // x fp16
__device__ __half g_wa [(size_t)3*C_*C_];   // W_attn fp16
__device__ __half g_wp [(size_t)C_*C_];     // W_proj fp16
__device__ __half g_qf [(size_t)M_*3*C_];   // qkv fp16
__device__ __half g_af [(size_t)M_*C_];     // attn out fp16

// ---------------------------------------------------------------------------
// helpers
// ---------------------------------------------------------------------------
__device__ __forceinline__ uint32_t smem_u32(const void* p) {
    uint32_t a;
    asm("{ .reg .u64 t; cvta.to.shared.u64 t, %1; cvt.u32.u64 %0, t; }"
        : "=r"(a) : "l"(p));
    return a;
}
__device__ __forceinline__ void cp16(uint32_t dst, const void* src) {
    asm volatile("cp.async.cg.shared.global [%0], [%1], 16;" :: "r"(dst), "l"(src));
}
#define CP_COMMIT() asm volatile("cp.async.commit_group;" ::: "memory")
#define CP_WAIT0()  asm volatile("cp.async.wait_group 0;" ::: "memory")
#define CP_WAIT1()  asm volatile("cp.async.wait_group 1;" ::: "memory")

__device__ __forceinline__ void ldm_x4(uint32_t* r, uint32_t addr) {
    asm volatile("ldmatrix.sync.aligned.m8n8.x4.shared.b16 {%0,%1,%2,%3}, [%4];"
                 : "=r"(r[0]), "=r"(r[1]), "=r"(r[2]), "=r"(r[3]) : "r"(addr));
}
__device__ __forceinline__ void ldm_x4_t(uint32_t* r, uint32_t addr) {
    asm volatile("ldmatrix.sync.aligned.m8n8.x4.trans.shared.b16 {%0,%1,%2,%3}, [%4];"
                 : "=r"(r[0]), "=r"(r[1]), "=r"(r[2]), "=r"(r[3]) : "r"(addr));
}
__device__ __forceinline__ void mma_f16(float* c, const uint32_t* a, const uint32_t* b) {
    asm volatile(
        "mma.sync.aligned.m16n8k16.row.col.f32.f16.f16.f32 "
        "{%0,%1,%2,%3}, {%4,%5,%6,%7}, {%8,%9}, {%0,%1,%2,%3};"
        : "+f"(c[0]), "+f"(c[1]), "+f"(c[2]), "+f"(c[3])
        : "r"(a[0]), "r"(a[1]), "r"(a[2]), "r"(a[3]), "r"(b[0]), "r"(b[1]));
}
__device__ __forceinline__ uint32_t pack_h2(float a, float b) {
    __half2 v = __floats2half2_rn(a, b);
    return *(uint32_t*)&v;
}

// ---------------------------------------------------------------------------
// fp32 -> fp16 conversion
// ---------------------------------------------------------------------------
__global__ __launch_bounds__(256) void conv_f32_h(const float* __restrict__ src,
                                                  __half* __restrict__ h, int n4) {
    int i = blockIdx.x * 256 + threadIdx.x;
    if (i >= n4) return;
    float4 v = *(const float4*)&src[(size_t)i * 4];
    __half hh[4] = {__float2half_rn(v.x), __float2half_rn(v.y),
                    __float2half_rn(v.z), __float2half_rn(v.w)};
    *(uint2*)&h[(size_t)i * 4] = *(uint2*)hh;
}

// ---------------------------------------------------------------------------
// GEMM:  C[M,N] = A[M,K] @ B[N,K]^T    (single-pass fp16)
// 128x256 tile, BK=32, 512 threads (16 warps, 4x4; warp tile 32x64).
// 3-stage cp.async pipeline (90 KB smem).
// OUT_MODE: 0 = fp32, 2 = fp16.
// ---------------------------------------------------------------------------
#define G_ROW   80
#define G_A     0
#define G_B     10240
#define G_STAGE 30720
#define G_SMEM  (3*G_STAGE)

__device__ __forceinline__ void gemm_issue(uint32_t sb,
                                           const __half* Af, const __half* Bf,
                                           int row0, int col0, int k0, int K, int t) {
    // A: 128 rows x 4 segs = 512 slots -> one per thread
    {
        int r = t >> 2, s = t & 3;
        uint32_t d = sb + r * G_ROW + s * 16;
        size_t ga = (size_t)(row0 + r) * K + k0 + s * 8;
        cp16(d + G_A, Af + ga);
    }
    // B: 256 rows x 4 segs = 1024 slots -> two per thread
    #pragma unroll
    for (int p = 0; p < 2; p++) {
        int id = t + p * 512;
        int r = id >> 2, s = id & 3;
        uint32_t d = sb + r * G_ROW + s * 16;
        size_t gb = (size_t)(col0 + r) * K + k0 + s * 8;
        cp16(d + G_B, Bf + gb);
    }
}

template<int OUT_MODE>
__global__ __launch_bounds__(512, 1) void gemm_f16(const __half* __restrict__ Af,
                                                   const __half* __restrict__ Bf,
                                                   float* __restrict__ Cf,
                                                   __half* __restrict__ Ch16,
                                                   int M, int N, int K) {
    extern __shared__ __align__(16) char dyn[];
    const uint32_t sbase = smem_u32(dyn);

    const int t    = threadIdx.x;
    const int lane = t & 31;
    const int wid  = t >> 5;
    const int wm   = (wid >> 2) * 32;
    const int wn   = (wid & 3) * 64;
    const int row0 = blockIdx.y * 128;
    const int col0 = blockIdx.x * 256;
    const int lrow = lane & 15;
    const int lkof = (lane >> 4) << 3;

    float acc[2][8][4];
    #pragma unroll
    for (int i = 0; i < 2; i++)
        #pragma unroll
        for (int j = 0; j < 8; j++)
            #pragma unroll
            for (int q = 0; q < 4; q++) acc[i][j][q] = 0.f;

    const int nchunk = K / 32;   // 24

    gemm_issue(sbase, Af, Bf, row0, col0, 0, K, t);
    CP_COMMIT();
    gemm_issue(sbase + G_STAGE, Af, Bf, row0, col0, 32, K, t);
    CP_COMMIT();

    int stage = 0;
    for (int ch = 0; ch < nchunk; ++ch) {
        if (ch + 1 < nchunk) { CP_WAIT1(); } else { CP_WAIT0(); }
        __syncthreads();
        if (ch + 2 < nchunk) {
            int ns = stage + 2; if (ns >= 3) ns -= 3;
            gemm_issue(sbase + ns * G_STAGE, Af, Bf,
                       row0, col0, (ch + 2) * 32, K, t);
            CP_COMMIT();
        }
        const uint32_t sb = sbase + stage * G_STAGE;
        if (++stage == 3) stage = 0;

        #pragma unroll
        for (int ks = 0; ks < 2; ks++) {
            const int kb = ks * 16 + lkof;

            uint32_t af[2][4];
            #pragma unroll
            for (int mf = 0; mf < 2; mf++) {
                uint32_t aoff = (uint32_t)((wm + mf * 16 + lrow) * G_ROW + kb * 2);
                ldm_x4(af[mf], sb + G_A + aoff);
            }
            #pragma unroll
            for (int nn = 0; nn < 4; nn++) {
                uint32_t boff = (uint32_t)((wn + nn * 16 + lrow) * G_ROW + kb * 2);
                uint32_t rb[4];
                ldm_x4(rb, sb + G_B + boff);
                uint32_t b0[2] = {rb[0], rb[2]};
                uint32_t b1[2] = {rb[1], rb[3]};
                #pragma unroll
                for (int mf = 0; mf < 2; mf++) {
                    mma_f16(acc[mf][2*nn],   af[mf], b0);
                    mma_f16(acc[mf][2*nn+1], af[mf], b1);
                }
            }
        }
        // no bottom barrier: this stage is rewritten only after the next
        // iteration's top barrier (all warps done reading it).
    }

    #pragma unroll
    for (int mf = 0; mf < 2; mf++) {
        const int row = row0 + wm + mf * 16 + (lane >> 2);
        #pragma unroll
        for (int nf = 0; nf < 8; nf++) {
            const int col = col0 + wn + nf * 8 + (lane & 3) * 2;
            if (OUT_MODE == 2) {
                #pragma unroll
                for (int half_ = 0; half_ < 2; half_++) {
                    const size_t o = (size_t)(row + half_ * 8) * N + col;
                    __half2 hv = __floats2half2_rn(acc[mf][nf][2*half_],
                                                   acc[mf][nf][2*half_ + 1]);
                    *(__half2*)&Ch16[o] = hv;
                }
            } else {
                *(float2*)&Cf[(size_t)row * N + col] =
                    make_float2(acc[mf][nf][0], acc[mf][nf][1]);
                *(float2*)&Cf[(size_t)(row + 8) * N + col] =
                    make_float2(acc[mf][nf][2], acc[mf][nf][3]);
            }
        }
    }
}

// ---------------------------------------------------------------------------
// Flash attention, causal, single-pass fp16 mma, cp.async double-buffered K/V.
// CTA: 128 queries x (head,batch); 8 warps; 16 q-rows/warp; register softmax.
// Writes a single fp16 plane for the proj GEMM.
// ---------------------------------------------------------------------------
#define A_ROW   144
#define A_K     0
#define A_V     9216
#define A_STAGE 18432
#define A_SMEM  (2*A_STAGE)

__device__ __forceinline__ void attn_issue(uint32_t sb, const __half* qf,
                                           size_t base, int k0, int kcol, int vcol, int t) {
    #pragma unroll
    for (int p = 0; p < 2; p++) {
        int id = t + p * 256;
        int r = id >> 3, s = id & 7;
        size_t gk = base + (size_t)(k0 + r) * QKV_STRIDE + kcol + s * 8;
        size_t gv = base + (size_t)(k0 + r) * QKV_STRIDE + vcol + s * 8;
        uint32_t d = sb + r * A_ROW + s * 16;
        cp16(d + A_K, qf + gk);
        cp16(d + A_V, qf + gv);
    }
}

__global__ __launch_bounds__(256) void attn_mma(const __half* __restrict__ qf16,
                                                __half* __restrict__ of) {
    extern __shared__ __align__(16) char dyn[];
    const uint32_t sbase = smem_u32(dyn);

    const int t    = threadIdx.x;
    const int lane = t & 31;
    const int w    = t >> 5;
    const int q0   = (gridDim.x - 1 - blockIdx.x) * 128;   // heavy blocks first
    const int h    = blockIdx.y;
    const int b    = blockIdx.z;
    const size_t base = (size_t)b * T_ * QKV_STRIDE;
    const int qcol = h * HD;
    const int kcol = C_ + h * HD;
    const int vcol = 2 * C_ + h * HD;
    const int lrow = lane & 15;
    const int lkof = (lane >> 4) << 3;

    // ---- stage Q (128x64 fp16) into stage 0, frag to regs ----
    #pragma unroll
    for (int p = 0; p < 4; p++) {
        int id = t + p * 256;
        int r = id >> 3, s = id & 7;
        size_t g = base + (size_t)(q0 + r) * QKV_STRIDE + qcol + s * 8;
        uint32_t d = sbase + (r < 64 ? A_K + r * A_ROW : A_V + (r - 64) * A_ROW) + s * 16;
        cp16(d, qf16 + g);
    }
    CP_COMMIT();
    CP_WAIT0();
    __syncthreads();

    uint32_t qf[4][4];
    {
        const uint32_t bq = sbase + (w < 4 ? A_K : A_V);
        const uint32_t rofs = (uint32_t)(((w & 3) * 16 + lrow) * A_ROW);
        #pragma unroll
        for (int ks = 0; ks < 4; ks++) {
            uint32_t co = (uint32_t)((ks * 16 + lkof) * 2);
            ldm_x4(qf[ks], bq + rofs + co);
        }
    }
    __syncthreads();

    float mA = -1e30f, mB = -1e30f, lA = 0.f, lB = 0.f;
    float oacc[8][4];
    #pragma unroll
    for (int i = 0; i < 8; i++)
        #pragma unroll
        for (int j = 0; j < 4; j++) oacc[i][j] = 0.f;

    const int rowA = q0 + w * 16 + (lane >> 2);
    const int rowmax = q0 + w * 16 + 15;
    const int ntiles = q0 / 64 + 2;

    attn_issue(sbase, qf16, base, 0, kcol, vcol, t);
    CP_COMMIT();

    for (int kt = 0; kt < ntiles; kt++) {
        const int k0 = kt * 64;
        CP_WAIT0();
        __syncthreads();
        if (kt + 1 < ntiles) {
            attn_issue(sbase + ((kt + 1) & 1) * A_STAGE, qf16, base,
                       (kt + 1) * 64, kcol, vcol, t);
            CP_COMMIT();
        }
        const uint32_t sb = sbase + (kt & 1) * A_STAGE;

        if (k0 <= rowmax) {
            // ---- S = Q K^T ----
            float sacc[8][4];
            #pragma unroll
            for (int i = 0; i < 8; i++)
                #pragma unroll
                for (int j = 0; j < 4; j++) sacc[i][j] = 0.f;

            #pragma unroll
            for (int ks = 0; ks < 4; ks++) {
                const uint32_t co = (uint32_t)((ks * 16 + lkof) * 2);
                #pragma unroll
                for (int nn = 0; nn < 4; nn++) {
                    uint32_t ro = (uint32_t)((nn * 16 + lrow) * A_ROW);
                    uint32_t rh[4];
                    ldm_x4(rh, sb + A_K + ro + co);
                    uint32_t k0f[2] = {rh[0], rh[2]};
                    uint32_t k1f[2] = {rh[1], rh[3]};
                    mma_f16(sacc[2*nn],   qf[ks], k0f);
                    mma_f16(sacc[2*nn+1], qf[ks], k1f);
                }
            }

            // ---- scale + causal mask ----
            const bool need_mask = (k0 + 63 > q0 + w * 16);
            #pragma unroll
            for (int nf = 0; nf < 8; nf++) {
                #pragma unroll
                for (int j = 0; j < 4; j++) sacc[nf][j] *= 0.125f;
                if (need_mask) {
                    const int col = k0 + nf * 8 + (lane & 3) * 2;
                    if (col     > rowA)     sacc[nf][0] = -1e30f;
                    if (col + 1 > rowA)     sacc[nf][1] = -1e30f;
                    if (col     > rowA + 8) sacc[nf][2] = -1e30f;
                    if (col + 1 > rowA + 8) sacc[nf][3] = -1e30f;
                }
            }

            // ---- online softmax ----
            float tmA = -1e30f, tmB = -1e30f;
            #pragma unroll
            for (int nf = 0; nf < 8; nf++) {
                tmA = fmaxf(tmA, fmaxf(sacc[nf][0], sacc[nf][1]));
                tmB = fmaxf(tmB, fmaxf(sacc[nf][2], sacc[nf][3]));
            }
            tmA = fmaxf(tmA, __shfl_xor_sync(0xffffffffu, tmA, 1));
            tmA = fmaxf(tmA, __shfl_xor_sync(0xffffffffu, tmA, 2));
            tmB = fmaxf(tmB, __shfl_xor_sync(0xffffffffu, tmB, 1));
            tmB = fmaxf(tmB, __shfl_xor_sync(0xffffffffu, tmB, 2));

            const float mnA = fmaxf(mA, tmA);
            const float mnB = fmaxf(mB, tmB);
            const float aA = __expf(mA - mnA);
            const float aB = __expf(mB - mnB);

            float sumA = 0.f, sumB = 0.f;
            #pragma unroll
            for (int nf = 0; nf < 8; nf++) {
                sacc[nf][0] = __expf(sacc[nf][0] - mnA);
                sacc[nf][1] = __expf(sacc[nf][1] - mnA);
                sacc[nf][2] = __expf(sacc[nf][2] - mnB);
                sacc[nf][3] = __expf(sacc[nf][3] - mnB);
                sumA += sacc[nf][0] + sacc[nf][1];
                sumB += sacc[nf][2] + sacc[nf][3];
            }
            sumA += __shfl_xor_sync(0xffffffffu, sumA, 1);
            sumA += __shfl_xor_sync(0xffffffffu, sumA, 2);
            sumB += __shfl_xor_sync(0xffffffffu, sumB, 1);
            sumB += __shfl_xor_sync(0xffffffffu, sumB, 2);

            lA = lA * aA + sumA;  mA = mnA;
            lB = lB * aB + sumB;  mB = mnB;

            #pragma unroll
            for (int nf = 0; nf < 8; nf++) {
                oacc[nf][0] *= aA; oacc[nf][1] *= aA;
                oacc[nf][2] *= aB; oacc[nf][3] *= aB;
            }

            // ---- O += P V ----
            #pragma unroll
            for (int ks = 0; ks < 4; ks++) {
                uint32_t ph[4];
                ph[0] = pack_h2(sacc[2*ks][0],   sacc[2*ks][1]);
                ph[1] = pack_h2(sacc[2*ks][2],   sacc[2*ks][3]);
                ph[2] = pack_h2(sacc[2*ks+1][0], sacc[2*ks+1][1]);
                ph[3] = pack_h2(sacc[2*ks+1][2], sacc[2*ks+1][3]);

                const uint32_t krofs = (uint32_t)((ks * 16 + lrow) * A_ROW);
                #pragma unroll
                for (int nn = 0; nn < 4; nn++) {
                    uint32_t co = (uint32_t)((nn * 16 + lkof) * 2);
                    uint32_t vf[4];
                    ldm_x4_t(vf, sb + A_V + krofs + co);
                    uint32_t b0[2] = {vf[0], vf[1]};
                    uint32_t b1[2] = {vf[2], vf[3]};
                    mma_f16(oacc[2*nn],   ph, b0);
                    mma_f16(oacc[2*nn+1], ph, b1);
                }
            }
        }
    }

    // ---- epilogue: normalize, write fp16 ----
    const float invA = 1.f / lA;
    const float invB = 1.f / lB;
    const size_t orowA = ((size_t)b * T_ + rowA) * C_ + h * HD;
    #pragma unroll
    for (int nf = 0; nf < 8; nf++) {
        const int col = nf * 8 + (lane & 3) * 2;
        #pragma unroll
        for (int half_ = 0; half_ < 2; half_++) {
            const size_t o = orowA + half_ * 8 * C_ + col;
            __half2 hv = __floats2half2_rn(oacc[nf][2*half_]     * (half_ ? invB : invA),
                                           oacc[nf][2*half_ + 1] * (half_ ? invB : invA));
            *(__half2*)&of[o] = hv;
        }
    }
}

// ===========================================================================
extern "C" void kernel_launch(void* const* d_in, const int* in_sizes, int n_in,
                              void* d_out, int out_size) {
    const float* x      = (const float*)d_in[0];   // [B,T,C]
    const float* W_attn = (const float*)d_in[1];   // [3C,C]
    const float* W_proj = (const float*)d_in[2];   // [C,C]
    float* out = (float*)d_out;                    // [B,T,C]

    __half *xf, *wa, *wp, *qf, *af;
    cudaGetSymbolAddress((void**)&xf, g_xf);
    cudaGetSymbolAddress((void**)&wa, g_wa); cudaGetSymbolAddress((void**)&wp, g_wp);
    cudaGetSymbolAddress((void**)&qf, g_qf);
    cudaGetSymbolAddress((void**)&af, g_af);

    cudaFuncSetAttribute(gemm_f16<2>, cudaFuncAttributeMaxDynamicSharedMemorySize, G_SMEM);
    cudaFuncSetAttribute(gemm_f16<0>, cudaFuncAttributeMaxDynamicSharedMemorySize, G_SMEM);
    cudaFuncSetAttribute(attn_mma,    cudaFuncAttributeMaxDynamicSharedMemorySize, A_SMEM);

    // 0) conversions
    {
        int n4;
        n4 = M_ * C_ / 4;      conv_f32_h<<<(n4 + 255) / 256, 256>>>(x,      xf, n4);
        n4 = 3 * C_ * C_ / 4;  conv_f32_h<<<(n4 + 255) / 256, 256>>>(W_attn, wa, n4);
        n4 = C_ * C_ / 4;      conv_f32_h<<<(n4 + 255) / 256, 256>>>(W_proj, wp, n4);
    }

    // 1) qkv = x @ W_attn^T  -> fp16   [4096 x 2304]
    gemm_f16<2><<<dim3((3*C_)/256, M_/128), 512, G_SMEM>>>(
        xf, wa, nullptr, qf, M_, 3*C_, C_);

    // 2) causal attention (fp16) -> fp16
    attn_mma<<<dim3(T_/128, NH, B_), 256, A_SMEM>>>(qf, af);

    // 3) out = attn @ W_proj^T -> fp32   [4096 x 768]
    gemm_f16<0><<<dim3(C_/256, M_/128), 512, G_SMEM>>>(
        af, wp, out, nullptr, M_, C_, C_);
}

// round 14
// speedup vs baseline: 1.4495x; 1.0323x over previous
#include <cuda_runtime.h>
#include <cuda_bf16.h>
#include <cuda_fp16.h>
#include <cstdint>
#include <math.h>

#define B_  2
#define T_  2048
#define C_  768
#define NH  12
#define HD  64
#define QKV_STRIDE (3*C_)
#define M_  (B_*T_)          // 4096

// scale * log2(e): softmax computed in exp2 domain
#define SCL2 (0.125f * 1.4426950408889634f)

// ---------------------------------------------------------------------------
// Scratch (allocation-free rule: __device__ globals). All fp16 single planes.
// ---------------------------------------------------------------------------
__device__ __half g_xf [(size_t)M_*C_];     // x fp16
__device__ __half g_wa [(size_t)3*C_*C_];   // W_attn fp16
__device__ __half g_wp [(size_t)C_*C_];     // W_proj fp16
__device__ __half g_qf [(size_t)M_*3*C_];   // qkv fp16
__device__ __half g_af [(size_t)M_*C_];     // attn out fp16

// ---------------------------------------------------------------------------
// helpers
// ---------------------------------------------------------------------------
__device__ __forceinline__ uint32_t smem_u32(const void* p) {
    uint32_t a;
    asm("{ .reg .u64 t; cvta.to.shared.u64 t, %1; cvt.u32.u64 %0, t; }"
        : "=r"(a) : "l"(p));
    return a;
}
__device__ __forceinline__ void cp16(uint32_t dst, const void* src) {
    asm volatile("cp.async.cg.shared.global [%0], [%1], 16;" :: "r"(dst), "l"(src));
}
#define CP_COMMIT() asm volatile("cp.async.commit_group;" ::: "memory")
#define CP_WAIT0()  asm volatile("cp.async.wait_group 0;" ::: "memory")
#define CP_WAIT1()  asm volatile("cp.async.wait_group 1;" ::: "memory")

__device__ __forceinline__ void ldm_x4(uint32_t* r, uint32_t addr) {
    asm volatile("ldmatrix.sync.aligned.m8n8.x4.shared.b16 {%0,%1,%2,%3}, [%4];"
                 : "=r"(r[0]), "=r"(r[1]), "=r"(r[2]), "=r"(r[3]) : "r"(addr));
}
__device__ __forceinline__ void ldm_x4_t(uint32_t* r, uint32_t addr) {
    asm volatile("ldmatrix.sync.aligned.m8n8.x4.trans.shared.b16 {%0,%1,%2,%3}, [%4];"
                 : "=r"(r[0]), "=r"(r[1]), "=r"(r[2]), "=r"(r[3]) : "r"(addr));
}
__device__ __forceinline__ void mma_f16(float* c, const uint32_t* a, const uint32_t* b) {
    asm volatile(
        "mma.sync.aligned.m16n8k16.row.col.f32.f16.f16.f32 "
        "{%0,%1,%2,%3}, {%4,%5,%6,%7}, {%8,%9}, {%0,%1,%2,%3};"
        : "+f"(c[0]), "+f"(c[1]), "+f"(c[2]), "+f"(c[3])
        : "r"(a[0]), "r"(a[1]), "r"(a[2]), "r"(a[3]), "r"(b[0]), "r"(b[1]));
}
__device__ __forceinline__ uint32_t pack_h2(float a, float b) {
    __half2 v = __floats2half2_rn(a, b);
    return *(uint32_t*)&v;
}

// ---------------------------------------------------------------------------
// fp32 -> fp16 conversion
// ---------------------------------------------------------------------------
__global__ __launch_bounds__(256) void conv_f32_h(const float* __restrict__ src,
                                                  __half* __restrict__ h, int n4) {
    int i = blockIdx.x * 256 + threadIdx.x;
    if (i >= n4) return;
    float4 v = *(const float4*)&src[(size_t)i * 4];
    __half hh[4] = {__float2half_rn(v.x), __float2half_rn(v.y),
                    __float2half_rn(v.z), __float2half_rn(v.w)};
    *(uint2*)&h[(size_t)i * 4] = *(uint2*)hh;
}

// ---------------------------------------------------------------------------
// GEMM:  C[M,N] = A[M,K] @ B[N,K]^T    (single-pass fp16)   [unchanged R13]
// 128x256 tile, BK=32, 512 threads; 3-stage cp.async pipeline.
// OUT_MODE: 0 = fp32, 2 = fp16.
// ---------------------------------------------------------------------------
#define G_ROW   80
#define G_A     0
#define G_B     10240
#define G_STAGE 30720
#define G_SMEM  (3*G_STAGE)

__device__ __forceinline__ void gemm_issue(uint32_t sb,
                                           const __half* Af, const __half* Bf,
                                           int row0, int col0, int k0, int K, int t) {
    {
        int r = t >> 2, s = t & 3;
        uint32_t d = sb + r * G_ROW + s * 16;
        size_t ga = (size_t)(row0 + r) * K + k0 + s * 8;
        cp16(d + G_A, Af + ga);
    }
    #pragma unroll
    for (int p = 0; p < 2; p++) {
        int id = t + p * 512;
        int r = id >> 2, s = id & 3;
        uint32_t d = sb + r * G_ROW + s * 16;
        size_t gb = (size_t)(col0 + r) * K + k0 + s * 8;
        cp16(d + G_B, Bf + gb);
    }
}

template<int OUT_MODE>
__global__ __launch_bounds__(512, 1) void gemm_f16(const __half* __restrict__ Af,
                                                   const __half* __restrict__ Bf,
                                                   float* __restrict__ Cf,
                                                   __half* __restrict__ Ch16,
                                                   int M, int N, int K) {
    extern __shared__ __align__(16) char dyn[];
    const uint32_t sbase = smem_u32(dyn);

    const int t    = threadIdx.x;
    const int lane = t & 31;
    const int wid  = t >> 5;
    const int wm   = (wid >> 2) * 32;
    const int wn   = (wid & 3) * 64;
    const int row0 = blockIdx.y * 128;
    const int col0 = blockIdx.x * 256;
    const int lrow = lane & 15;
    const int lkof = (lane >> 4) << 3;

    float acc[2][8][4];
    #pragma unroll
    for (int i = 0; i < 2; i++)
        #pragma unroll
        for (int j = 0; j < 8; j++)
            #pragma unroll
            for (int q = 0; q < 4; q++) acc[i][j][q] = 0.f;

    const int nchunk = K / 32;   // 24

    gemm_issue(sbase, Af, Bf, row0, col0, 0, K, t);
    CP_COMMIT();
    gemm_issue(sbase + G_STAGE, Af, Bf, row0, col0, 32, K, t);
    CP_COMMIT();

    int stage = 0;
    for (int ch = 0; ch < nchunk; ++ch) {
        if (ch + 1 < nchunk) { CP_WAIT1(); } else { CP_WAIT0(); }
        __syncthreads();
        if (ch + 2 < nchunk) {
            int ns = stage + 2; if (ns >= 3) ns -= 3;
            gemm_issue(sbase + ns * G_STAGE, Af, Bf,
                       row0, col0, (ch + 2) * 32, K, t);
            CP_COMMIT();
        }
        const uint32_t sb = sbase + stage * G_STAGE;
        if (++stage == 3) stage = 0;

        #pragma unroll
        for (int ks = 0; ks < 2; ks++) {
            const int kb = ks * 16 + lkof;

            uint32_t af[2][4];
            #pragma unroll
            for (int mf = 0; mf < 2; mf++) {
                uint32_t aoff = (uint32_t)((wm + mf * 16 + lrow) * G_ROW + kb * 2);
                ldm_x4(af[mf], sb + G_A + aoff);
            }
            #pragma unroll
            for (int nn = 0; nn < 4; nn++) {
                uint32_t boff = (uint32_t)((wn + nn * 16 + lrow) * G_ROW + kb * 2);
                uint32_t rb[4];
                ldm_x4(rb, sb + G_B + boff);
                uint32_t b0[2] = {rb[0], rb[2]};
                uint32_t b1[2] = {rb[1], rb[3]};
                #pragma unroll
                for (int mf = 0; mf < 2; mf++) {
                    mma_f16(acc[mf][2*nn],   af[mf], b0);
                    mma_f16(acc[mf][2*nn+1], af[mf], b1);
                }
            }
        }
    }

    #pragma unroll
    for (int mf = 0; mf < 2; mf++) {
        const int row = row0 + wm + mf * 16 + (lane >> 2);
        #pragma unroll
        for (int nf = 0; nf < 8; nf++) {
            const int col = col0 + wn + nf * 8 + (lane & 3) * 2;
            if (OUT_MODE == 2) {
                #pragma unroll
                for (int half_ = 0; half_ < 2; half_++) {
                    const size_t o = (size_t)(row + half_ * 8) * N + col;
                    __half2 hv = __floats2half2_rn(acc[mf][nf][2*half_],
                                                   acc[mf][nf][2*half_ + 1]);
                    *(__half2*)&Ch16[o] = hv;
                }
            } else {
                *(float2*)&Cf[(size_t)row * N + col] =
                    make_float2(acc[mf][nf][0], acc[mf][nf][1]);
                *(float2*)&Cf[(size_t)(row + 8) * N + col] =
                    make_float2(acc[mf][nf][2], acc[mf][nf][3]);
            }
        }
    }
}

// ---------------------------------------------------------------------------
// Flash attention, causal, fp16 mma, cp.async double-buffered K/V.
// CTA: 128 queries x (head,batch); 8 warps; 2 CTAs/SM (MUFU/HMMA overlap).
// exp2-domain softmax; fine-grained causal mma skip.
// ---------------------------------------------------------------------------
#define A_ROW   144
#define A_K     0
#define A_V     9216
#define A_STAGE 18432
#define A_SMEM  (2*A_STAGE)

__device__ __forceinline__ void attn_issue(uint32_t sb, const __half* qf,
                                           size_t base, int k0, int kcol, int vcol, int t) {
    #pragma unroll
    for (int p = 0; p < 2; p++) {
        int id = t + p * 256;
        int r = id >> 3, s = id & 7;
        size_t gk = base + (size_t)(k0 + r) * QKV_STRIDE + kcol + s * 8;
        size_t gv = base + (size_t)(k0 + r) * QKV_STRIDE + vcol + s * 8;
        uint32_t d = sb + r * A_ROW + s * 16;
        cp16(d + A_K, qf + gk);
        cp16(d + A_V, qf + gv);
    }
}

__global__ __launch_bounds__(256, 2) void attn_mma(const __half* __restrict__ qf16,
                                                   __half* __restrict__ of) {
    extern __shared__ __align__(16) char dyn[];
    const uint32_t sbase = smem_u32(dyn);

    const int t    = threadIdx.x;
    const int lane = t & 31;
    const int w    = t >> 5;
    const int q0   = (gridDim.x - 1 - blockIdx.x) * 128;   // heavy blocks first
    const int h    = blockIdx.y;
    const int b    = blockIdx.z;
    const size_t base = (size_t)b * T_ * QKV_STRIDE;
    const int qcol = h * HD;
    const int kcol = C_ + h * HD;
    const int vcol = 2 * C_ + h * HD;
    const int lrow = lane & 15;
    const int lkof = (lane >> 4) << 3;

    // ---- stage Q (128x64 fp16) into stage 0, frag to regs ----
    #pragma unroll
    for (int p = 0; p < 4; p++) {
        int id = t + p * 256;
        int r = id >> 3, s = id & 7;
        size_t g = base + (size_t)(q0 + r) * QKV_STRIDE + qcol + s * 8;
        uint32_t d = sbase + (r < 64 ? A_K + r * A_ROW : A_V + (r - 64) * A_ROW) + s * 16;
        cp16(d, qf16 + g);
    }
    CP_COMMIT();
    CP_WAIT0();
    __syncthreads();

    uint32_t qf[4][4];
    {
        const uint32_t bq = sbase + (w < 4 ? A_K : A_V);
        const uint32_t rofs = (uint32_t)(((w & 3) * 16 + lrow) * A_ROW);
        #pragma unroll
        for (int ks = 0; ks < 4; ks++) {
            uint32_t co = (uint32_t)((ks * 16 + lkof) * 2);
            ldm_x4(qf[ks], bq + rofs + co);
        }
    }
    __syncthreads();

    float mA = -1e30f, mB = -1e30f, lA = 0.f, lB = 0.f;
    float oacc[8][4];
    #pragma unroll
    for (int i = 0; i < 8; i++)
        #pragma unroll
        for (int j = 0; j < 4; j++) oacc[i][j] = 0.f;

    const int rowA = q0 + w * 16 + (lane >> 2);
    const int rowmax = q0 + w * 16 + 15;
    const int ntiles = q0 / 64 + 2;

    attn_issue(sbase, qf16, base, 0, kcol, vcol, t);
    CP_COMMIT();

    for (int kt = 0; kt < ntiles; kt++) {
        const int k0 = kt * 64;
        CP_WAIT0();
        __syncthreads();
        if (kt + 1 < ntiles) {
            attn_issue(sbase + ((kt + 1) & 1) * A_STAGE, qf16, base,
                       (kt + 1) * 64, kcol, vcol, t);
            CP_COMMIT();
        }
        const uint32_t sb = sbase + (kt & 1) * A_STAGE;

        if (k0 <= rowmax) {
            const bool need_mask = (k0 + 63 > q0 + w * 16);

            // ---- S = Q K^T  (skip fully-masked nn columns in diagonal tiles) ----
            float sacc[8][4];
            #pragma unroll
            for (int i = 0; i < 8; i++)
                #pragma unroll
                for (int j = 0; j < 4; j++) sacc[i][j] = 0.f;

            #pragma unroll
            for (int ks = 0; ks < 4; ks++) {
                const uint32_t co = (uint32_t)((ks * 16 + lkof) * 2);
                #pragma unroll
                for (int nn = 0; nn < 4; nn++) {
                    if (k0 + nn * 16 <= rowmax) {
                        uint32_t ro = (uint32_t)((nn * 16 + lrow) * A_ROW);
                        uint32_t rh[4];
                        ldm_x4(rh, sb + A_K + ro + co);
                        uint32_t k0f[2] = {rh[0], rh[2]};
                        uint32_t k1f[2] = {rh[1], rh[3]};
                        mma_f16(sacc[2*nn],   qf[ks], k0f);
                        mma_f16(sacc[2*nn+1], qf[ks], k1f);
                    }
                }
            }

            // ---- scale (exp2 domain) + causal mask ----
            #pragma unroll
            for (int nf = 0; nf < 8; nf++) {
                #pragma unroll
                for (int j = 0; j < 4; j++) sacc[nf][j] *= SCL2;
                if (need_mask) {
                    const int col = k0 + nf * 8 + (lane & 3) * 2;
                    if (col     > rowA)     sacc[nf][0] = -1e30f;
                    if (col + 1 > rowA)     sacc[nf][1] = -1e30f;
                    if (col     > rowA + 8) sacc[nf][2] = -1e30f;
                    if (col + 1 > rowA + 8) sacc[nf][3] = -1e30f;
                }
            }

            // ---- online softmax (exp2 domain) ----
            float tmA = -1e30f, tmB = -1e30f;
            #pragma unroll
            for (int nf = 0; nf < 8; nf++) {
                tmA = fmaxf(tmA, fmaxf(sacc[nf][0], sacc[nf][1]));
                tmB = fmaxf(tmB, fmaxf(sacc[nf][2], sacc[nf][3]));
            }
            tmA = fmaxf(tmA, __shfl_xor_sync(0xffffffffu, tmA, 1));
            tmA = fmaxf(tmA, __shfl_xor_sync(0xffffffffu, tmA, 2));
            tmB = fmaxf(tmB, __shfl_xor_sync(0xffffffffu, tmB, 1));
            tmB = fmaxf(tmB, __shfl_xor_sync(0xffffffffu, tmB, 2));

            const float mnA = fmaxf(mA, tmA);
            const float mnB = fmaxf(mB, tmB);
            const float aA = exp2f(mA - mnA);
            const float aB = exp2f(mB - mnB);

            float sumA = 0.f, sumB = 0.f;
            #pragma unroll
            for (int nf = 0; nf < 8; nf++) {
                sacc[nf][0] = exp2f(sacc[nf][0] - mnA);
                sacc[nf][1] = exp2f(sacc[nf][1] - mnA);
                sacc[nf][2] = exp2f(sacc[nf][2] - mnB);
                sacc[nf][3] = exp2f(sacc[nf][3] - mnB);
                sumA += sacc[nf][0] + sacc[nf][1];
                sumB += sacc[nf][2] + sacc[nf][3];
            }
            sumA += __shfl_xor_sync(0xffffffffu, sumA, 1);
            sumA += __shfl_xor_sync(0xffffffffu, sumA, 2);
            sumB += __shfl_xor_sync(0xffffffffu, sumB, 1);
            sumB += __shfl_xor_sync(0xffffffffu, sumB, 2);

            lA = lA * aA + sumA;  mA = mnA;
            lB = lB * aB + sumB;  mB = mnB;

            #pragma unroll
            for (int nf = 0; nf < 8; nf++) {
                oacc[nf][0] *= aA; oacc[nf][1] *= aA;
                oacc[nf][2] *= aB; oacc[nf][3] *= aB;
            }

            // ---- O += P V  (skip zero-P key chunks in diagonal tiles) ----
            #pragma unroll
            for (int ks = 0; ks < 4; ks++) {
                if (k0 + ks * 16 <= rowmax) {
                    uint32_t ph[4];
                    ph[0] = pack_h2(sacc[2*ks][0],   sacc[2*ks][1]);
                    ph[1] = pack_h2(sacc[2*ks][2],   sacc[2*ks][3]);
                    ph[2] = pack_h2(sacc[2*ks+1][0], sacc[2*ks+1][1]);
                    ph[3] = pack_h2(sacc[2*ks+1][2], sacc[2*ks+1][3]);

                    const uint32_t krofs = (uint32_t)((ks * 16 + lrow) * A_ROW);
                    #pragma unroll
                    for (int nn = 0; nn < 4; nn++) {
                        uint32_t co = (uint32_t)((nn * 16 + lkof) * 2);
                        uint32_t vf[4];
                        ldm_x4_t(vf, sb + A_V + krofs + co);
                        uint32_t b0[2] = {vf[0], vf[1]};
                        uint32_t b1[2] = {vf[2], vf[3]};
                        mma_f16(oacc[2*nn],   ph, b0);
                        mma_f16(oacc[2*nn+1], ph, b1);
                    }
                }
            }
        }
    }

    // ---- epilogue: normalize, write fp16 ----
    const float invA = 1.f / lA;
    const float invB = 1.f / lB;
    const size_t orowA = ((size_t)b * T_ + rowA) * C_ + h * HD;
    #pragma unroll
    for (int nf = 0; nf < 8; nf++) {
        const int col = nf * 8 + (lane & 3) * 2;
        #pragma unroll
        for (int half_ = 0; half_ < 2; half_++) {
            const size_t o = orowA + half_ * 8 * C_ + col;
            __half2 hv = __floats2half2_rn(oacc[nf][2*half_]     * (half_ ? invB : invA),
                                           oacc[nf][2*half_ + 1] * (half_ ? invB : invA));
            *(__half2*)&of[o] = hv;
        }
    }
}

// ===========================================================================
extern "C" void kernel_launch(void* const* d_in, const int* in_sizes, int n_in,
                              void* d_out, int out_size) {
    const float* x      = (const float*)d_in[0];   // [B,T,C]
    const float* W_attn = (const float*)d_in[1];   // [3C,C]
    const float* W_proj = (const float*)d_in[2];   // [C,C]
    float* out = (float*)d_out;                    // [B,T,C]

    __half *xf, *wa, *wp, *qf, *af;
    cudaGetSymbolAddress((void**)&xf, g_xf);
    cudaGetSymbolAddress((void**)&wa, g_wa); cudaGetSymbolAddress((void**)&wp, g_wp);
    cudaGetSymbolAddress((void**)&qf, g_qf);
    cudaGetSymbolAddress((void**)&af, g_af);

    cudaFuncSetAttribute(gemm_f16<2>, cudaFuncAttributeMaxDynamicSharedMemorySize, G_SMEM);
    cudaFuncSetAttribute(gemm_f16<0>, cudaFuncAttributeMaxDynamicSharedMemorySize, G_SMEM);
    cudaFuncSetAttribute(attn_mma,    cudaFuncAttributeMaxDynamicSharedMemorySize, A_SMEM);

    // 0) conversions
    {
        int n4;
        n4 = M_ * C_ / 4;      conv_f32_h<<<(n4 + 255) / 256, 256>>>(x,      xf, n4);
        n4 = 3 * C_ * C_ / 4;  conv_f32_h<<<(n4 + 255) / 256, 256>>>(W_attn, wa, n4);
        n4 = C_ * C_ / 4;      conv_f32_h<<<(n4 + 255) / 256, 256>>>(W_proj, wp, n4);
    }

    // 1) qkv = x @ W_attn^T  -> fp16   [4096 x 2304]
    gemm_f16<2><<<dim3((3*C_)/256, M_/128), 512, G_SMEM>>>(
        xf, wa, nullptr, qf, M_, 3*C_, C_);

    // 2) causal attention (fp16) -> fp16
    attn_mma<<<dim3(T_/128, NH, B_), 256, A_SMEM>>>(qf, af);

    // 3) out = attn @ W_proj^T -> fp32   [4096 x 768]
    gemm_f16<0><<<dim3(C_/256, M_/128), 512, G_SMEM>>>(
        af, wp, out, nullptr, M_, C_, C_);
}

// round 15
// speedup vs baseline: 1.5005x; 1.0352x over previous
#include <cuda_runtime.h>
#include <cuda_bf16.h>
#include <cuda_fp16.h>
#include <cstdint>
#include <math.h>

#define B_  2
#define T_  2048
#define C_  768
#define NH  12
#define HD  64
#define QKV_STRIDE (3*C_)
#define M_  (B_*T_)          // 4096

#define SCL2 (0.125f * 1.4426950408889634f)

// ---------------------------------------------------------------------------
// Scratch (allocation-free rule: __device__ globals). All fp16 single planes.
// ---------------------------------------------------------------------------
__device__ __half g_xf [(size_t)M_*C_];
__device__ __half g_wa [(size_t)3*C_*C_];
__device__ __half g_wp [(size_t)C_*C_];
__device__ __half g_qf [(size_t)M_*3*C_];
__device__ __half g_af [(size_t)M_*C_];

// ---------------------------------------------------------------------------
// helpers
// ---------------------------------------------------------------------------
__device__ __forceinline__ uint32_t smem_u32(const void* p) {
    uint32_t a;
    asm("{ .reg .u64 t; cvta.to.shared.u64 t, %1; cvt.u32.u64 %0, t; }"
        : "=r"(a) : "l"(p));
    return a;
}
__device__ __forceinline__ void cp16(uint32_t dst, const void* src) {
    asm volatile("cp.async.cg.shared.global [%0], [%1], 16;" :: "r"(dst), "l"(src));
}
#define CP_COMMIT() asm volatile("cp.async.commit_group;" ::: "memory")
#define CP_WAIT0()  asm volatile("cp.async.wait_group 0;" ::: "memory")
#define CP_WAIT1()  asm volatile("cp.async.wait_group 1;" ::: "memory")

__device__ __forceinline__ void ldm_x4(uint32_t* r, uint32_t addr) {
    asm volatile("ldmatrix.sync.aligned.m8n8.x4.shared.b16 {%0,%1,%2,%3}, [%4];"
                 : "=r"(r[0]), "=r"(r[1]), "=r"(r[2]), "=r"(r[3]) : "r"(addr));
}
__device__ __forceinline__ void ldm_x4_t(uint32_t* r, uint32_t addr) {
    asm volatile("ldmatrix.sync.aligned.m8n8.x4.trans.shared.b16 {%0,%1,%2,%3}, [%4];"
                 : "=r"(r[0]), "=r"(r[1]), "=r"(r[2]), "=r"(r[3]) : "r"(addr));
}
__device__ __forceinline__ void mma_f16(float* c, const uint32_t* a, const uint32_t* b) {
    asm volatile(
        "mma.sync.aligned.m16n8k16.row.col.f32.f16.f16.f32 "
        "{%0,%1,%2,%3}, {%4,%5,%6,%7}, {%8,%9}, {%0,%1,%2,%3};"
        : "+f"(c[0]), "+f"(c[1]), "+f"(c[2]), "+f"(c[3])
        : "r"(a[0]), "r"(a[1]), "r"(a[2]), "r"(a[3]), "r"(b[0]), "r"(b[1]));
}
__device__ __forceinline__ uint32_t pack_h2(float a, float b) {
    __half2 v = __floats2half2_rn(a, b);
    return *(uint32_t*)&v;
}

// ---------------------------------------------------------------------------
// fp32 -> fp16 conversion
// ---------------------------------------------------------------------------
__global__ __launch_bounds__(256) void conv_f32_h(const float* __restrict__ src,
                                                  __half* __restrict__ h, int n4) {
    int i = blockIdx.x * 256 + threadIdx.x;
    if (i >= n4) return;
    float4 v = *(const float4*)&src[(size_t)i * 4];
    __half hh[4] = {__float2half_rn(v.x), __float2half_rn(v.y),
                    __float2half_rn(v.z), __float2half_rn(v.w)};
    *(uint2*)&h[(size_t)i * 4] = *(uint2*)hh;
}

// ===========================================================================
// GEMM-BIG: C[M,N] = A @ B^T, 128x256 tile, BK=64, 512 threads, 3-stage.
// Used for GEMM1 (fp16 out).
// ===========================================================================
#define GB_ROW   144                    // 64 fp16 = 128B + 16B pad
#define GB_A     0
#define GB_B     18432                  // 128*144
#define GB_STAGE 55296                  // + 256*144
#define GB_SMEM  (3*GB_STAGE)

__device__ __forceinline__ void gemm_big_issue(uint32_t sb,
                                               const __half* Af, const __half* Bf,
                                               int row0, int col0, int k0, int K, int t) {
    // A: 128 rows x 8 segs = 1024 slots -> 2 per thread
    #pragma unroll
    for (int p = 0; p < 2; p++) {
        int id = t + p * 512;
        int r = id >> 3, s = id & 7;
        uint32_t d = sb + GB_A + r * GB_ROW + s * 16;
        cp16(d, Af + (size_t)(row0 + r) * K + k0 + s * 8);
    }
    // B: 256 rows x 8 segs = 2048 slots -> 4 per thread
    #pragma unroll
    for (int p = 0; p < 4; p++) {
        int id = t + p * 512;
        int r = id >> 3, s = id & 7;
        uint32_t d = sb + GB_B + r * GB_ROW + s * 16;
        cp16(d, Bf + (size_t)(col0 + r) * K + k0 + s * 8);
    }
}

__global__ __launch_bounds__(512, 1) void gemm_big(const __half* __restrict__ Af,
                                                   const __half* __restrict__ Bf,
                                                   __half* __restrict__ Ch16,
                                                   int M, int N, int K) {
    extern __shared__ __align__(16) char dyn[];
    const uint32_t sbase = smem_u32(dyn);

    const int t    = threadIdx.x;
    const int lane = t & 31;
    const int wid  = t >> 5;
    const int wm   = (wid >> 2) * 32;
    const int wn   = (wid & 3) * 64;
    const int row0 = blockIdx.y * 128;
    const int col0 = blockIdx.x * 256;
    const int lrow = lane & 15;
    const int lkof = (lane >> 4) << 3;

    float acc[2][8][4];
    #pragma unroll
    for (int i = 0; i < 2; i++)
        #pragma unroll
        for (int j = 0; j < 8; j++)
            #pragma unroll
            for (int q = 0; q < 4; q++) acc[i][j][q] = 0.f;

    const int nchunk = K / 64;   // 12

    gemm_big_issue(sbase, Af, Bf, row0, col0, 0, K, t);
    CP_COMMIT();
    gemm_big_issue(sbase + GB_STAGE, Af, Bf, row0, col0, 64, K, t);
    CP_COMMIT();

    int stage = 0;
    for (int ch = 0; ch < nchunk; ++ch) {
        if (ch + 1 < nchunk) { CP_WAIT1(); } else { CP_WAIT0(); }
        __syncthreads();
        if (ch + 2 < nchunk) {
            int ns = stage + 2; if (ns >= 3) ns -= 3;
            gemm_big_issue(sbase + ns * GB_STAGE, Af, Bf,
                           row0, col0, (ch + 2) * 64, K, t);
            CP_COMMIT();
        }
        const uint32_t sb = sbase + stage * GB_STAGE;
        if (++stage == 3) stage = 0;

        #pragma unroll
        for (int ks = 0; ks < 4; ks++) {
            const int kb = ks * 16 + lkof;

            uint32_t af[2][4];
            #pragma unroll
            for (int mf = 0; mf < 2; mf++) {
                uint32_t aoff = (uint32_t)((wm + mf * 16 + lrow) * GB_ROW + kb * 2);
                ldm_x4(af[mf], sb + GB_A + aoff);
            }
            #pragma unroll
            for (int nn = 0; nn < 4; nn++) {
                uint32_t boff = (uint32_t)((wn + nn * 16 + lrow) * GB_ROW + kb * 2);
                uint32_t rb[4];
                ldm_x4(rb, sb + GB_B + boff);
                uint32_t b0[2] = {rb[0], rb[2]};
                uint32_t b1[2] = {rb[1], rb[3]};
                #pragma unroll
                for (int mf = 0; mf < 2; mf++) {
                    mma_f16(acc[mf][2*nn],   af[mf], b0);
                    mma_f16(acc[mf][2*nn+1], af[mf], b1);
                }
            }
        }
    }

    #pragma unroll
    for (int mf = 0; mf < 2; mf++) {
        const int row = row0 + wm + mf * 16 + (lane >> 2);
        #pragma unroll
        for (int nf = 0; nf < 8; nf++) {
            const int col = col0 + wn + nf * 8 + (lane & 3) * 2;
            #pragma unroll
            for (int half_ = 0; half_ < 2; half_++) {
                const size_t o = (size_t)(row + half_ * 8) * N + col;
                __half2 hv = __floats2half2_rn(acc[mf][nf][2*half_],
                                               acc[mf][nf][2*half_ + 1]);
                *(__half2*)&Ch16[o] = hv;
            }
        }
    }
}

// ===========================================================================
// GEMM-SMALL: C[M,N] = A @ B^T, 128x128 tile, BK=64, 256 threads, 3-stage,
// 2 CTAs/SM. Used for GEMM2 (fp32 out) — doubles SM coverage on N=768.
// ===========================================================================
#define GS_ROW   144
#define GS_A     0
#define GS_B     18432
#define GS_STAGE 36864
#define GS_SMEM  (3*GS_STAGE)

__device__ __forceinline__ void gemm_small_issue(uint32_t sb,
                                                 const __half* Af, const __half* Bf,
                                                 int row0, int col0, int k0, int K, int t) {
    #pragma unroll
    for (int p = 0; p < 4; p++) {
        int id = t + p * 256;
        int r = id >> 3, s = id & 7;
        cp16(sb + GS_A + r * GS_ROW + s * 16, Af + (size_t)(row0 + r) * K + k0 + s * 8);
        cp16(sb + GS_B + r * GS_ROW + s * 16, Bf + (size_t)(col0 + r) * K + k0 + s * 8);
    }
}

__global__ __launch_bounds__(256, 2) void gemm_small(const __half* __restrict__ Af,
                                                     const __half* __restrict__ Bf,
                                                     float* __restrict__ Cf,
                                                     int M, int N, int K) {
    extern __shared__ __align__(16) char dyn[];
    const uint32_t sbase = smem_u32(dyn);

    const int t    = threadIdx.x;
    const int lane = t & 31;
    const int wid  = t >> 5;
    const int wm   = (wid >> 2) * 64;   // 2 M groups of 64
    const int wn   = (wid & 3) * 32;    // 4 N groups of 32
    const int row0 = blockIdx.y * 128;
    const int col0 = blockIdx.x * 128;
    const int lrow = lane & 15;
    const int lkof = (lane >> 4) << 3;

    float acc[4][4][4];
    #pragma unroll
    for (int i = 0; i < 4; i++)
        #pragma unroll
        for (int j = 0; j < 4; j++)
            #pragma unroll
            for (int q = 0; q < 4; q++) acc[i][j][q] = 0.f;

    const int nchunk = K / 64;   // 12

    gemm_small_issue(sbase, Af, Bf, row0, col0, 0, K, t);
    CP_COMMIT();
    gemm_small_issue(sbase + GS_STAGE, Af, Bf, row0, col0, 64, K, t);
    CP_COMMIT();

    int stage = 0;
    for (int ch = 0; ch < nchunk; ++ch) {
        if (ch + 1 < nchunk) { CP_WAIT1(); } else { CP_WAIT0(); }
        __syncthreads();
        if (ch + 2 < nchunk) {
            int ns = stage + 2; if (ns >= 3) ns -= 3;
            gemm_small_issue(sbase + ns * GS_STAGE, Af, Bf,
                             row0, col0, (ch + 2) * 64, K, t);
            CP_COMMIT();
        }
        const uint32_t sb = sbase + stage * GS_STAGE;
        if (++stage == 3) stage = 0;

        #pragma unroll
        for (int ks = 0; ks < 4; ks++) {
            const int kb = ks * 16 + lkof;

            uint32_t af[4][4];
            #pragma unroll
            for (int mf = 0; mf < 4; mf++) {
                uint32_t aoff = (uint32_t)((wm + mf * 16 + lrow) * GS_ROW + kb * 2);
                ldm_x4(af[mf], sb + GS_A + aoff);
            }
            #pragma unroll
            for (int nn = 0; nn < 2; nn++) {
                uint32_t boff = (uint32_t)((wn + nn * 16 + lrow) * GS_ROW + kb * 2);
                uint32_t rb[4];
                ldm_x4(rb, sb + GS_B + boff);
                uint32_t b0[2] = {rb[0], rb[2]};
                uint32_t b1[2] = {rb[1], rb[3]};
                #pragma unroll
                for (int mf = 0; mf < 4; mf++) {
                    mma_f16(acc[mf][2*nn],   af[mf], b0);
                    mma_f16(acc[mf][2*nn+1], af[mf], b1);
                }
            }
        }
    }

    #pragma unroll
    for (int mf = 0; mf < 4; mf++) {
        const int row = row0 + wm + mf * 16 + (lane >> 2);
        #pragma unroll
        for (int nf = 0; nf < 4; nf++) {
            const int col = col0 + wn + nf * 8 + (lane & 3) * 2;
            *(float2*)&Cf[(size_t)row * N + col] =
                make_float2(acc[mf][nf][0], acc[mf][nf][1]);
            *(float2*)&Cf[(size_t)(row + 8) * N + col] =
                make_float2(acc[mf][nf][2], acc[mf][nf][3]);
        }
    }
}

// ---------------------------------------------------------------------------
// Flash attention (unchanged from R14): causal, fp16 mma, 2 CTAs/SM,
// exp2-domain softmax, fine-grained causal skip.
// ---------------------------------------------------------------------------
#define A_ROW   144
#define A_K     0
#define A_V     9216
#define A_STAGE 18432
#define A_SMEM  (2*A_STAGE)

__device__ __forceinline__ void attn_issue(uint32_t sb, const __half* qf,
                                           size_t base, int k0, int kcol, int vcol, int t) {
    #pragma unroll
    for (int p = 0; p < 2; p++) {
        int id = t + p * 256;
        int r = id >> 3, s = id & 7;
        size_t gk = base + (size_t)(k0 + r) * QKV_STRIDE + kcol + s * 8;
        size_t gv = base + (size_t)(k0 + r) * QKV_STRIDE + vcol + s * 8;
        uint32_t d = sb + r * A_ROW + s * 16;
        cp16(d + A_K, qf + gk);
        cp16(d + A_V, qf + gv);
    }
}

__global__ __launch_bounds__(256, 2) void attn_mma(const __half* __restrict__ qf16,
                                                   __half* __restrict__ of) {
    extern __shared__ __align__(16) char dyn[];
    const uint32_t sbase = smem_u32(dyn);

    const int t    = threadIdx.x;
    const int lane = t & 31;
    const int w    = t >> 5;
    const int q0   = (gridDim.x - 1 - blockIdx.x) * 128;
    const int h    = blockIdx.y;
    const int b    = blockIdx.z;
    const size_t base = (size_t)b * T_ * QKV_STRIDE;
    const int qcol = h * HD;
    const int kcol = C_ + h * HD;
    const int vcol = 2 * C_ + h * HD;
    const int lrow = lane & 15;
    const int lkof = (lane >> 4) << 3;

    #pragma unroll
    for (int p = 0; p < 4; p++) {
        int id = t + p * 256;
        int r = id >> 3, s = id & 7;
        size_t g = base + (size_t)(q0 + r) * QKV_STRIDE + qcol + s * 8;
        uint32_t d = sbase + (r < 64 ? A_K + r * A_ROW : A_V + (r - 64) * A_ROW) + s * 16;
        cp16(d, qf16 + g);
    }
    CP_COMMIT();
    CP_WAIT0();
    __syncthreads();

    uint32_t qf[4][4];
    {
        const uint32_t bq = sbase + (w < 4 ? A_K : A_V);
        const uint32_t rofs = (uint32_t)(((w & 3) * 16 + lrow) * A_ROW);
        #pragma unroll
        for (int ks = 0; ks < 4; ks++) {
            uint32_t co = (uint32_t)((ks * 16 + lkof) * 2);
            ldm_x4(qf[ks], bq + rofs + co);
        }
    }
    __syncthreads();

    float mA = -1e30f, mB = -1e30f, lA = 0.f, lB = 0.f;
    float oacc[8][4];
    #pragma unroll
    for (int i = 0; i < 8; i++)
        #pragma unroll
        for (int j = 0; j < 4; j++) oacc[i][j] = 0.f;

    const int rowA = q0 + w * 16 + (lane >> 2);
    const int rowmax = q0 + w * 16 + 15;
    const int ntiles = q0 / 64 + 2;

    attn_issue(sbase, qf16, base, 0, kcol, vcol, t);
    CP_COMMIT();

    for (int kt = 0; kt < ntiles; kt++) {
        const int k0 = kt * 64;
        CP_WAIT0();
        __syncthreads();
        if (kt + 1 < ntiles) {
            attn_issue(sbase + ((kt + 1) & 1) * A_STAGE, qf16, base,
                       (kt + 1) * 64, kcol, vcol, t);
            CP_COMMIT();
        }
        const uint32_t sb = sbase + (kt & 1) * A_STAGE;

        if (k0 <= rowmax) {
            const bool need_mask = (k0 + 63 > q0 + w * 16);

            float sacc[8][4];
            #pragma unroll
            for (int i = 0; i < 8; i++)
                #pragma unroll
                for (int j = 0; j < 4; j++) sacc[i][j] = 0.f;

            #pragma unroll
            for (int ks = 0; ks < 4; ks++) {
                const uint32_t co = (uint32_t)((ks * 16 + lkof) * 2);
                #pragma unroll
                for (int nn = 0; nn < 4; nn++) {
                    if (k0 + nn * 16 <= rowmax) {
                        uint32_t ro = (uint32_t)((nn * 16 + lrow) * A_ROW);
                        uint32_t rh[4];
                        ldm_x4(rh, sb + A_K + ro + co);
                        uint32_t k0f[2] = {rh[0], rh[2]};
                        uint32_t k1f[2] = {rh[1], rh[3]};
                        mma_f16(sacc[2*nn],   qf[ks], k0f);
                        mma_f16(sacc[2*nn+1], qf[ks], k1f);
                    }
                }
            }

            #pragma unroll
            for (int nf = 0; nf < 8; nf++) {
                #pragma unroll
                for (int j = 0; j < 4; j++) sacc[nf][j] *= SCL2;
                if (need_mask) {
                    const int col = k0 + nf * 8 + (lane & 3) * 2;
                    if (col     > rowA)     sacc[nf][0] = -1e30f;
                    if (col + 1 > rowA)     sacc[nf][1] = -1e30f;
                    if (col     > rowA + 8) sacc[nf][2] = -1e30f;
                    if (col + 1 > rowA + 8) sacc[nf][3] = -1e30f;
                }
            }

            float tmA = -1e30f, tmB = -1e30f;
            #pragma unroll
            for (int nf = 0; nf < 8; nf++) {
                tmA = fmaxf(tmA, fmaxf(sacc[nf][0], sacc[nf][1]));
                tmB = fmaxf(tmB, fmaxf(sacc[nf][2], sacc[nf][3]));
            }
            tmA = fmaxf(tmA, __shfl_xor_sync(0xffffffffu, tmA, 1));
            tmA = fmaxf(tmA, __shfl_xor_sync(0xffffffffu, tmA, 2));
            tmB = fmaxf(tmB, __shfl_xor_sync(0xffffffffu, tmB, 1));
            tmB = fmaxf(tmB, __shfl_xor_sync(0xffffffffu, tmB, 2));

            const float mnA = fmaxf(mA, tmA);
            const float mnB = fmaxf(mB, tmB);
            const float aA = exp2f(mA - mnA);
            const float aB = exp2f(mB - mnB);

            float sumA = 0.f, sumB = 0.f;
            #pragma unroll
            for (int nf = 0; nf < 8; nf++) {
                sacc[nf][0] = exp2f(sacc[nf][0] - mnA);
                sacc[nf][1] = exp2f(sacc[nf][1] - mnA);
                sacc[nf][2] = exp2f(sacc[nf][2] - mnB);
                sacc[nf][3] = exp2f(sacc[nf][3] - mnB);
                sumA += sacc[nf][0] + sacc[nf][1];
                sumB += sacc[nf][2] + sacc[nf][3];
            }
            sumA += __shfl_xor_sync(0xffffffffu, sumA, 1);
            sumA += __shfl_xor_sync(0xffffffffu, sumA, 2);
            sumB += __shfl_xor_sync(0xffffffffu, sumB, 1);
            sumB += __shfl_xor_sync(0xffffffffu, sumB, 2);

            lA = lA * aA + sumA;  mA = mnA;
            lB = lB * aB + sumB;  mB = mnB;

            #pragma unroll
            for (int nf = 0; nf < 8; nf++) {
                oacc[nf][0] *= aA; oacc[nf][1] *= aA;
                oacc[nf][2] *= aB; oacc[nf][3] *= aB;
            }

            #pragma unroll
            for (int ks = 0; ks < 4; ks++) {
                if (k0 + ks * 16 <= rowmax) {
                    uint32_t ph[4];
                    ph[0] = pack_h2(sacc[2*ks][0],   sacc[2*ks][1]);
                    ph[1] = pack_h2(sacc[2*ks][2],   sacc[2*ks][3]);
                    ph[2] = pack_h2(sacc[2*ks+1][0], sacc[2*ks+1][1]);
                    ph[3] = pack_h2(sacc[2*ks+1][2], sacc[2*ks+1][3]);

                    const uint32_t krofs = (uint32_t)((ks * 16 + lrow) * A_ROW);
                    #pragma unroll
                    for (int nn = 0; nn < 4; nn++) {
                        uint32_t co = (uint32_t)((nn * 16 + lkof) * 2);
                        uint32_t vf[4];
                        ldm_x4_t(vf, sb + A_V + krofs + co);
                        uint32_t b0[2] = {vf[0], vf[1]};
                        uint32_t b1[2] = {vf[2], vf[3]};
                        mma_f16(oacc[2*nn],   ph, b0);
                        mma_f16(oacc[2*nn+1], ph, b1);
                    }
                }
            }
        }
    }

    const float invA = 1.f / lA;
    const float invB = 1.f / lB;
    const size_t orowA = ((size_t)b * T_ + rowA) * C_ + h * HD;
    #pragma unroll
    for (int nf = 0; nf < 8; nf++) {
        const int col = nf * 8 + (lane & 3) * 2;
        #pragma unroll
        for (int half_ = 0; half_ < 2; half_++) {
            const size_t o = orowA + half_ * 8 * C_ + col;
            __half2 hv = __floats2half2_rn(oacc[nf][2*half_]     * (half_ ? invB : invA),
                                           oacc[nf][2*half_ + 1] * (half_ ? invB : invA));
            *(__half2*)&of[o] = hv;
        }
    }
}

// ===========================================================================
extern "C" void kernel_launch(void* const* d_in, const int* in_sizes, int n_in,
                              void* d_out, int out_size) {
    const float* x      = (const float*)d_in[0];   // [B,T,C]
    const float* W_attn = (const float*)d_in[1];   // [3C,C]
    const float* W_proj = (const float*)d_in[2];   // [C,C]
    float* out = (float*)d_out;                    // [B,T,C]

    __half *xf, *wa, *wp, *qf, *af;
    cudaGetSymbolAddress((void**)&xf, g_xf);
    cudaGetSymbolAddress((void**)&wa, g_wa); cudaGetSymbolAddress((void**)&wp, g_wp);
    cudaGetSymbolAddress((void**)&qf, g_qf);
    cudaGetSymbolAddress((void**)&af, g_af);

    cudaFuncSetAttribute(gemm_big,   cudaFuncAttributeMaxDynamicSharedMemorySize, GB_SMEM);
    cudaFuncSetAttribute(gemm_small, cudaFuncAttributeMaxDynamicSharedMemorySize, GS_SMEM);
    cudaFuncSetAttribute(attn_mma,   cudaFuncAttributeMaxDynamicSharedMemorySize, A_SMEM);

    // 0) conversions
    {
        int n4;
        n4 = M_ * C_ / 4;      conv_f32_h<<<(n4 + 255) / 256, 256>>>(x,      xf, n4);
        n4 = 3 * C_ * C_ / 4;  conv_f32_h<<<(n4 + 255) / 256, 256>>>(W_attn, wa, n4);
        n4 = C_ * C_ / 4;      conv_f32_h<<<(n4 + 255) / 256, 256>>>(W_proj, wp, n4);
    }

    // 1) qkv = x @ W_attn^T  -> fp16   [4096 x 2304]
    gemm_big<<<dim3((3*C_)/256, M_/128), 512, GB_SMEM>>>(xf, wa, qf, M_, 3*C_, C_);

    // 2) causal attention (fp16) -> fp16
    attn_mma<<<dim3(T_/128, NH, B_), 256, A_SMEM>>>(qf, af);

    // 3) out = attn @ W_proj^T -> fp32   [4096 x 768], 192 CTAs for coverage
    gemm_small<<<dim3(C_/128, M_/128), 256, GS_SMEM>>>(af, wp, out, M_, C_, C_);
}

// round 16
// speedup vs baseline: 1.6241x; 1.0824x over previous
#include <cuda_runtime.h>
#include <cuda_bf16.h>
#include <cuda_fp16.h>
#include <cstdint>
#include <math.h>

#define B_  2
#define T_  2048
#define C_  768
#define NH  12
#define HD  64
#define QKV_STRIDE (3*C_)
#define M_  (B_*T_)          // 4096

#define SCL2 (0.125f * 1.4426950408889634f)

// ---------------------------------------------------------------------------
// Scratch (allocation-free rule: __device__ globals). All fp16 single planes.
// ---------------------------------------------------------------------------
__device__ __half g_xf [(size_t)M_*C_];
__device__ __half g_wa [(size_t)3*C_*C_];
__device__ __half g_wp [(size_t)C_*C_];
__device__ __half g_qf [(size_t)M_*3*C_];
__device__ __half g_af [(size_t)M_*C_];

// ---------------------------------------------------------------------------
// helpers
// ---------------------------------------------------------------------------
__device__ __forceinline__ uint32_t smem_u32(const void* p) {
    uint32_t a;
    asm("{ .reg .u64 t; cvta.to.shared.u64 t, %1; cvt.u32.u64 %0, t; }"
        : "=r"(a) : "l"(p));
    return a;
}
__device__ __forceinline__ void cp16(uint32_t dst, const void* src) {
    asm volatile("cp.async.cg.shared.global [%0], [%1], 16;" :: "r"(dst), "l"(src));
}
#define CP_COMMIT() asm volatile("cp.async.commit_group;" ::: "memory")
#define CP_WAIT0()  asm volatile("cp.async.wait_group 0;" ::: "memory")
#define CP_WAIT1()  asm volatile("cp.async.wait_group 1;" ::: "memory")

__device__ __forceinline__ void ldm_x4(uint32_t* r, uint32_t addr) {
    asm volatile("ldmatrix.sync.aligned.m8n8.x4.shared.b16 {%0,%1,%2,%3}, [%4];"
                 : "=r"(r[0]), "=r"(r[1]), "=r"(r[2]), "=r"(r[3]) : "r"(addr));
}
__device__ __forceinline__ void ldm_x4_t(uint32_t* r, uint32_t addr) {
    asm volatile("ldmatrix.sync.aligned.m8n8.x4.trans.shared.b16 {%0,%1,%2,%3}, [%4];"
                 : "=r"(r[0]), "=r"(r[1]), "=r"(r[2]), "=r"(r[3]) : "r"(addr));
}
__device__ __forceinline__ void mma_f16(float* c, const uint32_t* a, const uint32_t* b) {
    asm volatile(
        "mma.sync.aligned.m16n8k16.row.col.f32.f16.f16.f32 "
        "{%0,%1,%2,%3}, {%4,%5,%6,%7}, {%8,%9}, {%0,%1,%2,%3};"
        : "+f"(c[0]), "+f"(c[1]), "+f"(c[2]), "+f"(c[3])
        : "r"(a[0]), "r"(a[1]), "r"(a[2]), "r"(a[3]), "r"(b[0]), "r"(b[1]));
}
__device__ __forceinline__ uint32_t pack_h2(float a, float b) {
    __half2 v = __floats2half2_rn(a, b);
    return *(uint32_t*)&v;
}

// ---------------------------------------------------------------------------
// merged fp32 -> fp16 conversion (x, W_attn, W_proj in one launch)
// ---------------------------------------------------------------------------
#define N4_X  (M_*C_/4)
#define N4_WA (3*C_*C_/4)
#define N4_WP (C_*C_/4)
#define N4_TOT (N4_X + N4_WA + N4_WP)

__global__ __launch_bounds__(256) void conv_all(const float* __restrict__ x,
                                                const float* __restrict__ wa_in,
                                                const float* __restrict__ wp_in,
                                                __half* __restrict__ xf,
                                                __half* __restrict__ wa,
                                                __half* __restrict__ wp) {
    int i = blockIdx.x * 256 + threadIdx.x;
    if (i >= N4_TOT) return;
    const float* src;
    __half* dst;
    int j = i;
    if (j < N4_X)            { src = x;     dst = xf; }
    else if ((j -= N4_X) < N4_WA) { src = wa_in; dst = wa; }
    else                     { j -= N4_WA; src = wp_in; dst = wp; }
    float4 v = *(const float4*)&src[(size_t)j * 4];
    __half hh[4] = {__float2half_rn(v.x), __float2half_rn(v.y),
                    __float2half_rn(v.z), __float2half_rn(v.w)};
    *(uint2*)&dst[(size_t)j * 4] = *(uint2*)hh;
}

// ===========================================================================
// GEMM-BIG (unchanged R15): 128x256 tile, BK=64, 512 threads, 3-stage.
// ===========================================================================
#define GB_ROW   144
#define GB_A     0
#define GB_B     18432
#define GB_STAGE 55296
#define GB_SMEM  (3*GB_STAGE)

__device__ __forceinline__ void gemm_big_issue(uint32_t sb,
                                               const __half* Af, const __half* Bf,
                                               int row0, int col0, int k0, int K, int t) {
    #pragma unroll
    for (int p = 0; p < 2; p++) {
        int id = t + p * 512;
        int r = id >> 3, s = id & 7;
        cp16(sb + GB_A + r * GB_ROW + s * 16, Af + (size_t)(row0 + r) * K + k0 + s * 8);
    }
    #pragma unroll
    for (int p = 0; p < 4; p++) {
        int id = t + p * 512;
        int r = id >> 3, s = id & 7;
        cp16(sb + GB_B + r * GB_ROW + s * 16, Bf + (size_t)(col0 + r) * K + k0 + s * 8);
    }
}

__global__ __launch_bounds__(512, 1) void gemm_big(const __half* __restrict__ Af,
                                                   const __half* __restrict__ Bf,
                                                   __half* __restrict__ Ch16,
                                                   int M, int N, int K) {
    extern __shared__ __align__(16) char dyn[];
    const uint32_t sbase = smem_u32(dyn);

    const int t    = threadIdx.x;
    const int lane = t & 31;
    const int wid  = t >> 5;
    const int wm   = (wid >> 2) * 32;
    const int wn   = (wid & 3) * 64;
    const int row0 = blockIdx.y * 128;
    const int col0 = blockIdx.x * 256;
    const int lrow = lane & 15;
    const int lkof = (lane >> 4) << 3;

    float acc[2][8][4];
    #pragma unroll
    for (int i = 0; i < 2; i++)
        #pragma unroll
        for (int j = 0; j < 8; j++)
            #pragma unroll
            for (int q = 0; q < 4; q++) acc[i][j][q] = 0.f;

    const int nchunk = K / 64;

    gemm_big_issue(sbase, Af, Bf, row0, col0, 0, K, t);
    CP_COMMIT();
    gemm_big_issue(sbase + GB_STAGE, Af, Bf, row0, col0, 64, K, t);
    CP_COMMIT();

    int stage = 0;
    for (int ch = 0; ch < nchunk; ++ch) {
        if (ch + 1 < nchunk) { CP_WAIT1(); } else { CP_WAIT0(); }
        __syncthreads();
        if (ch + 2 < nchunk) {
            int ns = stage + 2; if (ns >= 3) ns -= 3;
            gemm_big_issue(sbase + ns * GB_STAGE, Af, Bf,
                           row0, col0, (ch + 2) * 64, K, t);
            CP_COMMIT();
        }
        const uint32_t sb = sbase + stage * GB_STAGE;
        if (++stage == 3) stage = 0;

        #pragma unroll
        for (int ks = 0; ks < 4; ks++) {
            const int kb = ks * 16 + lkof;

            uint32_t af[2][4];
            #pragma unroll
            for (int mf = 0; mf < 2; mf++) {
                uint32_t aoff = (uint32_t)((wm + mf * 16 + lrow) * GB_ROW + kb * 2);
                ldm_x4(af[mf], sb + GB_A + aoff);
            }
            #pragma unroll
            for (int nn = 0; nn < 4; nn++) {
                uint32_t boff = (uint32_t)((wn + nn * 16 + lrow) * GB_ROW + kb * 2);
                uint32_t rb[4];
                ldm_x4(rb, sb + GB_B + boff);
                uint32_t b0[2] = {rb[0], rb[2]};
                uint32_t b1[2] = {rb[1], rb[3]};
                #pragma unroll
                for (int mf = 0; mf < 2; mf++) {
                    mma_f16(acc[mf][2*nn],   af[mf], b0);
                    mma_f16(acc[mf][2*nn+1], af[mf], b1);
                }
            }
        }
    }

    #pragma unroll
    for (int mf = 0; mf < 2; mf++) {
        const int row = row0 + wm + mf * 16 + (lane >> 2);
        #pragma unroll
        for (int nf = 0; nf < 8; nf++) {
            const int col = col0 + wn + nf * 8 + (lane & 3) * 2;
            #pragma unroll
            for (int half_ = 0; half_ < 2; half_++) {
                const size_t o = (size_t)(row + half_ * 8) * N + col;
                __half2 hv = __floats2half2_rn(acc[mf][nf][2*half_],
                                               acc[mf][nf][2*half_ + 1]);
                *(__half2*)&Ch16[o] = hv;
            }
        }
    }
}

// ===========================================================================
// GEMM-SMALL (unchanged R15): 128x128, BK=64, 256 threads, 2 CTAs/SM, fp32 out.
// ===========================================================================
#define GS_ROW   144
#define GS_A     0
#define GS_B     18432
#define GS_STAGE 36864
#define GS_SMEM  (3*GS_STAGE)

__device__ __forceinline__ void gemm_small_issue(uint32_t sb,
                                                 const __half* Af, const __half* Bf,
                                                 int row0, int col0, int k0, int K, int t) {
    #pragma unroll
    for (int p = 0; p < 4; p++) {
        int id = t + p * 256;
        int r = id >> 3, s = id & 7;
        cp16(sb + GS_A + r * GS_ROW + s * 16, Af + (size_t)(row0 + r) * K + k0 + s * 8);
        cp16(sb + GS_B + r * GS_ROW + s * 16, Bf + (size_t)(col0 + r) * K + k0 + s * 8);
    }
}

__global__ __launch_bounds__(256, 2) void gemm_small(const __half* __restrict__ Af,
                                                     const __half* __restrict__ Bf,
                                                     float* __restrict__ Cf,
                                                     int M, int N, int K) {
    extern __shared__ __align__(16) char dyn[];
    const uint32_t sbase = smem_u32(dyn);

    const int t    = threadIdx.x;
    const int lane = t & 31;
    const int wid  = t >> 5;
    const int wm   = (wid >> 2) * 64;
    const int wn   = (wid & 3) * 32;
    const int row0 = blockIdx.y * 128;
    const int col0 = blockIdx.x * 128;
    const int lrow = lane & 15;
    const int lkof = (lane >> 4) << 3;

    float acc[4][4][4];
    #pragma unroll
    for (int i = 0; i < 4; i++)
        #pragma unroll
        for (int j = 0; j < 4; j++)
            #pragma unroll
            for (int q = 0; q < 4; q++) acc[i][j][q] = 0.f;

    const int nchunk = K / 64;

    gemm_small_issue(sbase, Af, Bf, row0, col0, 0, K, t);
    CP_COMMIT();
    gemm_small_issue(sbase + GS_STAGE, Af, Bf, row0, col0, 64, K, t);
    CP_COMMIT();

    int stage = 0;
    for (int ch = 0; ch < nchunk; ++ch) {
        if (ch + 1 < nchunk) { CP_WAIT1(); } else { CP_WAIT0(); }
        __syncthreads();
        if (ch + 2 < nchunk) {
            int ns = stage + 2; if (ns >= 3) ns -= 3;
            gemm_small_issue(sbase + ns * GS_STAGE, Af, Bf,
                             row0, col0, (ch + 2) * 64, K, t);
            CP_COMMIT();
        }
        const uint32_t sb = sbase + stage * GS_STAGE;
        if (++stage == 3) stage = 0;

        #pragma unroll
        for (int ks = 0; ks < 4; ks++) {
            const int kb = ks * 16 + lkof;

            uint32_t af[4][4];
            #pragma unroll
            for (int mf = 0; mf < 4; mf++) {
                uint32_t aoff = (uint32_t)((wm + mf * 16 + lrow) * GS_ROW + kb * 2);
                ldm_x4(af[mf], sb + GS_A + aoff);
            }
            #pragma unroll
            for (int nn = 0; nn < 2; nn++) {
                uint32_t boff = (uint32_t)((wn + nn * 16 + lrow) * GS_ROW + kb * 2);
                uint32_t rb[4];
                ldm_x4(rb, sb + GS_B + boff);
                uint32_t b0[2] = {rb[0], rb[2]};
                uint32_t b1[2] = {rb[1], rb[3]};
                #pragma unroll
                for (int mf = 0; mf < 4; mf++) {
                    mma_f16(acc[mf][2*nn],   af[mf], b0);
                    mma_f16(acc[mf][2*nn+1], af[mf], b1);
                }
            }
        }
    }

    #pragma unroll
    for (int mf = 0; mf < 4; mf++) {
        const int row = row0 + wm + mf * 16 + (lane >> 2);
        #pragma unroll
        for (int nf = 0; nf < 4; nf++) {
            const int col = col0 + wn + nf * 8 + (lane & 3) * 2;
            *(float2*)&Cf[(size_t)row * N + col] =
                make_float2(acc[mf][nf][0], acc[mf][nf][1]);
            *(float2*)&Cf[(size_t)(row + 8) * N + col] =
                make_float2(acc[mf][nf][2], acc[mf][nf][3]);
        }
    }
}

// ---------------------------------------------------------------------------
// Flash attention: causal, fp16 mma. NEW: 64-query CTAs, 4 warps, 4 CTAs/SM
// (independent-phase pipe mixing). Raw-domain max + fused FFMA+exp2.
// ---------------------------------------------------------------------------
#define A_ROW   144
#define A_K     0
#define A_V     9216
#define A_STAGE 18432
#define A_SMEM  (2*A_STAGE)

__device__ __forceinline__ void attn_issue(uint32_t sb, const __half* qf,
                                           size_t base, int k0, int kcol, int vcol, int t) {
    // K/V: 64 rows x 8 segs = 512 slots each; 128 threads -> 4 slots per thread
    #pragma unroll
    for (int p = 0; p < 4; p++) {
        int id = t + p * 128;
        int r = id >> 3, s = id & 7;
        size_t gk = base + (size_t)(k0 + r) * QKV_STRIDE + kcol + s * 8;
        size_t gv = base + (size_t)(k0 + r) * QKV_STRIDE + vcol + s * 8;
        uint32_t d = sb + r * A_ROW + s * 16;
        cp16(d + A_K, qf + gk);
        cp16(d + A_V, qf + gv);
    }
}

__global__ __launch_bounds__(128, 4) void attn_mma(const __half* __restrict__ qf16,
                                                   __half* __restrict__ of) {
    extern __shared__ __align__(16) char dyn[];
    const uint32_t sbase = smem_u32(dyn);

    const int t    = threadIdx.x;
    const int lane = t & 31;
    const int w    = t >> 5;                               // 0..3
    const int q0   = (gridDim.x - 1 - blockIdx.x) * 64;    // heavy blocks first
    const int h    = blockIdx.y;
    const int b    = blockIdx.z;
    const size_t base = (size_t)b * T_ * QKV_STRIDE;
    const int qcol = h * HD;
    const int kcol = C_ + h * HD;
    const int vcol = 2 * C_ + h * HD;
    const int lrow = lane & 15;
    const int lkof = (lane >> 4) << 3;

    // ---- stage Q (64x64 fp16) into stage-0 K area, frag to regs ----
    #pragma unroll
    for (int p = 0; p < 4; p++) {
        int id = t + p * 128;
        int r = id >> 3, s = id & 7;
        size_t g = base + (size_t)(q0 + r) * QKV_STRIDE + qcol + s * 8;
        cp16(sbase + A_K + r * A_ROW + s * 16, qf16 + g);
    }
    CP_COMMIT();
    CP_WAIT0();
    __syncthreads();

    uint32_t qf[4][4];
    {
        const uint32_t rofs = (uint32_t)((w * 16 + lrow) * A_ROW);
        #pragma unroll
        for (int ks = 0; ks < 4; ks++) {
            uint32_t co = (uint32_t)((ks * 16 + lkof) * 2);
            ldm_x4(qf[ks], sbase + A_K + rofs + co);
        }
    }
    __syncthreads();

    // raw-domain running max (mA_raw); l in P domain
    float mA = -1e30f, mB = -1e30f, lA = 0.f, lB = 0.f;
    float oacc[8][4];
    #pragma unroll
    for (int i = 0; i < 8; i++)
        #pragma unroll
        for (int j = 0; j < 4; j++) oacc[i][j] = 0.f;

    const int rowA = q0 + w * 16 + (lane >> 2);
    const int rowmax = q0 + w * 16 + 15;
    const int ntiles = q0 / 64 + 1;

    attn_issue(sbase, qf16, base, 0, kcol, vcol, t);
    CP_COMMIT();

    for (int kt = 0; kt < ntiles; kt++) {
        const int k0 = kt * 64;
        CP_WAIT0();
        __syncthreads();
        if (kt + 1 < ntiles) {
            attn_issue(sbase + ((kt + 1) & 1) * A_STAGE, qf16, base,
                       (kt + 1) * 64, kcol, vcol, t);
            CP_COMMIT();
        }
        const uint32_t sb = sbase + (kt & 1) * A_STAGE;

        if (k0 <= rowmax) {
            const bool need_mask = (k0 + 63 > q0 + w * 16);

            // ---- S = Q K^T (raw domain) ----
            float sacc[8][4];
            #pragma unroll
            for (int i = 0; i < 8; i++)
                #pragma unroll
                for (int j = 0; j < 4; j++) sacc[i][j] = 0.f;

            #pragma unroll
            for (int ks = 0; ks < 4; ks++) {
                const uint32_t co = (uint32_t)((ks * 16 + lkof) * 2);
                #pragma unroll
                for (int nn = 0; nn < 4; nn++) {
                    if (k0 + nn * 16 <= rowmax) {
                        uint32_t ro = (uint32_t)((nn * 16 + lrow) * A_ROW);
                        uint32_t rh[4];
                        ldm_x4(rh, sb + A_K + ro + co);
                        uint32_t k0f[2] = {rh[0], rh[2]};
                        uint32_t k1f[2] = {rh[1], rh[3]};
                        mma_f16(sacc[2*nn],   qf[ks], k0f);
                        mma_f16(sacc[2*nn+1], qf[ks], k1f);
                    }
                }
            }

            // ---- causal mask (raw domain) ----
            if (need_mask) {
                #pragma unroll
                for (int nf = 0; nf < 8; nf++) {
                    const int col = k0 + nf * 8 + (lane & 3) * 2;
                    if (col     > rowA)     sacc[nf][0] = -1e30f;
                    if (col + 1 > rowA)     sacc[nf][1] = -1e30f;
                    if (col     > rowA + 8) sacc[nf][2] = -1e30f;
                    if (col + 1 > rowA + 8) sacc[nf][3] = -1e30f;
                }
            }

            // ---- online softmax: max in raw domain, exp2 via fused FFMA ----
            float tmA = -1e30f, tmB = -1e30f;
            #pragma unroll
            for (int nf = 0; nf < 8; nf++) {
                tmA = fmaxf(tmA, fmaxf(sacc[nf][0], sacc[nf][1]));
                tmB = fmaxf(tmB, fmaxf(sacc[nf][2], sacc[nf][3]));
            }
            tmA = fmaxf(tmA, __shfl_xor_sync(0xffffffffu, tmA, 1));
            tmA = fmaxf(tmA, __shfl_xor_sync(0xffffffffu, tmA, 2));
            tmB = fmaxf(tmB, __shfl_xor_sync(0xffffffffu, tmB, 1));
            tmB = fmaxf(tmB, __shfl_xor_sync(0xffffffffu, tmB, 2));

            const float mnA = fmaxf(mA, tmA);
            const float mnB = fmaxf(mB, tmB);
            const float aA = exp2f((mA - mnA) * SCL2);
            const float aB = exp2f((mB - mnB) * SCL2);
            const float cA = mnA * SCL2;
            const float cB = mnB * SCL2;

            float sumA = 0.f, sumB = 0.f;
            #pragma unroll
            for (int nf = 0; nf < 8; nf++) {
                sacc[nf][0] = exp2f(fmaf(sacc[nf][0], SCL2, -cA));
                sacc[nf][1] = exp2f(fmaf(sacc[nf][1], SCL2, -cA));
                sacc[nf][2] = exp2f(fmaf(sacc[nf][2], SCL2, -cB));
                sacc[nf][3] = exp2f(fmaf(sacc[nf][3], SCL2, -cB));
                sumA += sacc[nf][0] + sacc[nf][1];
                sumB += sacc[nf][2] + sacc[nf][3];
            }
            sumA += __shfl_xor_sync(0xffffffffu, sumA, 1);
            sumA += __shfl_xor_sync(0xffffffffu, sumA, 2);
            sumB += __shfl_xor_sync(0xffffffffu, sumB, 1);
            sumB += __shfl_xor_sync(0xffffffffu, sumB, 2);

            lA = lA * aA + sumA;  mA = mnA;
            lB = lB * aB + sumB;  mB = mnB;

            #pragma unroll
            for (int nf = 0; nf < 8; nf++) {
                oacc[nf][0] *= aA; oacc[nf][1] *= aA;
                oacc[nf][2] *= aB; oacc[nf][3] *= aB;
            }

            // ---- O += P V ----
            #pragma unroll
            for (int ks = 0; ks < 4; ks++) {
                if (k0 + ks * 16 <= rowmax) {
                    uint32_t ph[4];
                    ph[0] = pack_h2(sacc[2*ks][0],   sacc[2*ks][1]);
                    ph[1] = pack_h2(sacc[2*ks][2],   sacc[2*ks][3]);
                    ph[2] = pack_h2(sacc[2*ks+1][0], sacc[2*ks+1][1]);
                    ph[3] = pack_h2(sacc[2*ks+1][2], sacc[2*ks+1][3]);

                    const uint32_t krofs = (uint32_t)((ks * 16 + lrow) * A_ROW);
                    #pragma unroll
                    for (int nn = 0; nn < 4; nn++) {
                        uint32_t co = (uint32_t)((nn * 16 + lkof) * 2);
                        uint32_t vf[4];
                        ldm_x4_t(vf, sb + A_V + krofs + co);
                        uint32_t b0[2] = {vf[0], vf[1]};
                        uint32_t b1[2] = {vf[2], vf[3]};
                        mma_f16(oacc[2*nn],   ph, b0);
                        mma_f16(oacc[2*nn+1], ph, b1);
                    }
                }
            }
        }
    }

    const float invA = 1.f / lA;
    const float invB = 1.f / lB;
    const size_t orowA = ((size_t)b * T_ + rowA) * C_ + h * HD;
    #pragma unroll
    for (int nf = 0; nf < 8; nf++) {
        const int col = nf * 8 + (lane & 3) * 2;
        #pragma unroll
        for (int half_ = 0; half_ < 2; half_++) {
            const size_t o = orowA + half_ * 8 * C_ + col;
            __half2 hv = __floats2half2_rn(oacc[nf][2*half_]     * (half_ ? invB : invA),
                                           oacc[nf][2*half_ + 1] * (half_ ? invB : invA));
            *(__half2*)&of[o] = hv;
        }
    }
}

// ===========================================================================
extern "C" void kernel_launch(void* const* d_in, const int* in_sizes, int n_in,
                              void* d_out, int out_size) {
    const float* x      = (const float*)d_in[0];   // [B,T,C]
    const float* W_attn = (const float*)d_in[1];   // [3C,C]
    const float* W_proj = (const float*)d_in[2];   // [C,C]
    float* out = (float*)d_out;                    // [B,T,C]

    __half *xf, *wa, *wp, *qf, *af;
    cudaGetSymbolAddress((void**)&xf, g_xf);
    cudaGetSymbolAddress((void**)&wa, g_wa); cudaGetSymbolAddress((void**)&wp, g_wp);
    cudaGetSymbolAddress((void**)&qf, g_qf);
    cudaGetSymbolAddress((void**)&af, g_af);

    cudaFuncSetAttribute(gemm_big,   cudaFuncAttributeMaxDynamicSharedMemorySize, GB_SMEM);
    cudaFuncSetAttribute(gemm_small, cudaFuncAttributeMaxDynamicSharedMemorySize, GS_SMEM);
    cudaFuncSetAttribute(attn_mma,   cudaFuncAttributeMaxDynamicSharedMemorySize, A_SMEM);

    // 0) conversions (single launch)
    conv_all<<<(N4_TOT + 255) / 256, 256>>>(x, W_attn, W_proj, xf, wa, wp);

    // 1) qkv = x @ W_attn^T  -> fp16   [4096 x 2304]
    gemm_big<<<dim3((3*C_)/256, M_/128), 512, GB_SMEM>>>(xf, wa, qf, M_, 3*C_, C_);

    // 2) causal attention (fp16) -> fp16   (64-query CTAs, 4/SM)
    attn_mma<<<dim3(T_/64, NH, B_), 128, A_SMEM>>>(qf, af);

    // 3) out = attn @ W_proj^T -> fp32   [4096 x 768]
    gemm_small<<<dim3(C_/128, M_/128), 256, GS_SMEM>>>(af, wp, out, M_, C_, C_);
}

// round 17
// speedup vs baseline: 1.6635x; 1.0243x over previous
#include <cuda_runtime.h>
#include <cuda_bf16.h>
#include <cuda_fp16.h>
#include <cstdint>
#include <math.h>

#define B_  2
#define T_  2048
#define C_  768
#define NH  12
#define HD  64
#define QKV_STRIDE (3*C_)
#define M_  (B_*T_)          // 4096

#define SCL2 (0.125f * 1.4426950408889634f)

// ---------------------------------------------------------------------------
// Scratch (allocation-free rule: __device__ globals). All fp16 single planes.
// ---------------------------------------------------------------------------
__device__ __half g_xf [(size_t)M_*C_];
__device__ __half g_wa [(size_t)3*C_*C_];
__device__ __half g_wp [(size_t)C_*C_];
__device__ __half g_qf [(size_t)M_*3*C_];
__device__ __half g_af [(size_t)M_*C_];

// ---------------------------------------------------------------------------
// helpers
// ---------------------------------------------------------------------------
__device__ __forceinline__ uint32_t smem_u32(const void* p) {
    uint32_t a;
    asm("{ .reg .u64 t; cvta.to.shared.u64 t, %1; cvt.u32.u64 %0, t; }"
        : "=r"(a) : "l"(p));
    return a;
}
__device__ __forceinline__ void cp16(uint32_t dst, const void* src) {
    asm volatile("cp.async.cg.shared.global [%0], [%1], 16;" :: "r"(dst), "l"(src));
}
#define CP_COMMIT() asm volatile("cp.async.commit_group;" ::: "memory")
#define CP_WAIT0()  asm volatile("cp.async.wait_group 0;" ::: "memory")
#define CP_WAIT1()  asm volatile("cp.async.wait_group 1;" ::: "memory")

__device__ __forceinline__ void ldm_x4(uint32_t* r, uint32_t addr) {
    asm volatile("ldmatrix.sync.aligned.m8n8.x4.shared.b16 {%0,%1,%2,%3}, [%4];"
                 : "=r"(r[0]), "=r"(r[1]), "=r"(r[2]), "=r"(r[3]) : "r"(addr));
}
__device__ __forceinline__ void ldm_x4_t(uint32_t* r, uint32_t addr) {
    asm volatile("ldmatrix.sync.aligned.m8n8.x4.trans.shared.b16 {%0,%1,%2,%3}, [%4];"
                 : "=r"(r[0]), "=r"(r[1]), "=r"(r[2]), "=r"(r[3]) : "r"(addr));
}
__device__ __forceinline__ void mma_f16(float* c, const uint32_t* a, const uint32_t* b) {
    asm volatile(
        "mma.sync.aligned.m16n8k16.row.col.f32.f16.f16.f32 "
        "{%0,%1,%2,%3}, {%4,%5,%6,%7}, {%8,%9}, {%0,%1,%2,%3};"
        : "+f"(c[0]), "+f"(c[1]), "+f"(c[2]), "+f"(c[3])
        : "r"(a[0]), "r"(a[1]), "r"(a[2]), "r"(a[3]), "r"(b[0]), "r"(b[1]));
}
__device__ __forceinline__ uint32_t pack_h2(float a, float b) {
    __half2 v = __floats2half2_rn(a, b);
    return *(uint32_t*)&v;
}

// ---------------------------------------------------------------------------
// merged fp32 -> fp16 conversion (x, W_attn, W_proj in one launch)
// ---------------------------------------------------------------------------
#define N4_X  (M_*C_/4)
#define N4_WA (3*C_*C_/4)
#define N4_WP (C_*C_/4)
#define N4_TOT (N4_X + N4_WA + N4_WP)

__global__ __launch_bounds__(256) void conv_all(const float* __restrict__ x,
                                                const float* __restrict__ wa_in,
                                                const float* __restrict__ wp_in,
                                                __half* __restrict__ xf,
                                                __half* __restrict__ wa,
                                                __half* __restrict__ wp) {
    int i = blockIdx.x * 256 + threadIdx.x;
    if (i >= N4_TOT) return;
    const float* src;
    __half* dst;
    int j = i;
    if (j < N4_X)            { src = x;     dst = xf; }
    else if ((j -= N4_X) < N4_WA) { src = wa_in; dst = wa; }
    else                     { j -= N4_WA; src = wp_in; dst = wp; }
    float4 v = *(const float4*)&src[(size_t)j * 4];
    __half hh[4] = {__float2half_rn(v.x), __float2half_rn(v.y),
                    __float2half_rn(v.z), __float2half_rn(v.w)};
    *(uint2*)&dst[(size_t)j * 4] = *(uint2*)hh;
}

// ===========================================================================
// GEMM-BIG (unchanged): 128x256 tile, BK=64, 512 threads, 3-stage.
// ===========================================================================
#define GB_ROW   144
#define GB_A     0
#define GB_B     18432
#define GB_STAGE 55296
#define GB_SMEM  (3*GB_STAGE)

__device__ __forceinline__ void gemm_big_issue(uint32_t sb,
                                               const __half* Af, const __half* Bf,
                                               int row0, int col0, int k0, int K, int t) {
    #pragma unroll
    for (int p = 0; p < 2; p++) {
        int id = t + p * 512;
        int r = id >> 3, s = id & 7;
        cp16(sb + GB_A + r * GB_ROW + s * 16, Af + (size_t)(row0 + r) * K + k0 + s * 8);
    }
    #pragma unroll
    for (int p = 0; p < 4; p++) {
        int id = t + p * 512;
        int r = id >> 3, s = id & 7;
        cp16(sb + GB_B + r * GB_ROW + s * 16, Bf + (size_t)(col0 + r) * K + k0 + s * 8);
    }
}

__global__ __launch_bounds__(512, 1) void gemm_big(const __half* __restrict__ Af,
                                                   const __half* __restrict__ Bf,
                                                   __half* __restrict__ Ch16,
                                                   int M, int N, int K) {
    extern __shared__ __align__(16) char dyn[];
    const uint32_t sbase = smem_u32(dyn);

    const int t    = threadIdx.x;
    const int lane = t & 31;
    const int wid  = t >> 5;
    const int wm   = (wid >> 2) * 32;
    const int wn   = (wid & 3) * 64;
    const int row0 = blockIdx.y * 128;
    const int col0 = blockIdx.x * 256;
    const int lrow = lane & 15;
    const int lkof = (lane >> 4) << 3;

    float acc[2][8][4];
    #pragma unroll
    for (int i = 0; i < 2; i++)
        #pragma unroll
        for (int j = 0; j < 8; j++)
            #pragma unroll
            for (int q = 0; q < 4; q++) acc[i][j][q] = 0.f;

    const int nchunk = K / 64;

    gemm_big_issue(sbase, Af, Bf, row0, col0, 0, K, t);
    CP_COMMIT();
    gemm_big_issue(sbase + GB_STAGE, Af, Bf, row0, col0, 64, K, t);
    CP_COMMIT();

    int stage = 0;
    for (int ch = 0; ch < nchunk; ++ch) {
        if (ch + 1 < nchunk) { CP_WAIT1(); } else { CP_WAIT0(); }
        __syncthreads();
        if (ch + 2 < nchunk) {
            int ns = stage + 2; if (ns >= 3) ns -= 3;
            gemm_big_issue(sbase + ns * GB_STAGE, Af, Bf,
                           row0, col0, (ch + 2) * 64, K, t);
            CP_COMMIT();
        }
        const uint32_t sb = sbase + stage * GB_STAGE;
        if (++stage == 3) stage = 0;

        #pragma unroll
        for (int ks = 0; ks < 4; ks++) {
            const int kb = ks * 16 + lkof;

            uint32_t af[2][4];
            #pragma unroll
            for (int mf = 0; mf < 2; mf++) {
                uint32_t aoff = (uint32_t)((wm + mf * 16 + lrow) * GB_ROW + kb * 2);
                ldm_x4(af[mf], sb + GB_A + aoff);
            }
            #pragma unroll
            for (int nn = 0; nn < 4; nn++) {
                uint32_t boff = (uint32_t)((wn + nn * 16 + lrow) * GB_ROW + kb * 2);
                uint32_t rb[4];
                ldm_x4(rb, sb + GB_B + boff);
                uint32_t b0[2] = {rb[0], rb[2]};
                uint32_t b1[2] = {rb[1], rb[3]};
                #pragma unroll
                for (int mf = 0; mf < 2; mf++) {
                    mma_f16(acc[mf][2*nn],   af[mf], b0);
                    mma_f16(acc[mf][2*nn+1], af[mf], b1);
                }
            }
        }
    }

    #pragma unroll
    for (int mf = 0; mf < 2; mf++) {
        const int row = row0 + wm + mf * 16 + (lane >> 2);
        #pragma unroll
        for (int nf = 0; nf < 8; nf++) {
            const int col = col0 + wn + nf * 8 + (lane & 3) * 2;
            #pragma unroll
            for (int half_ = 0; half_ < 2; half_++) {
                const size_t o = (size_t)(row + half_ * 8) * N + col;
                __half2 hv = __floats2half2_rn(acc[mf][nf][2*half_],
                                               acc[mf][nf][2*half_ + 1]);
                *(__half2*)&Ch16[o] = hv;
            }
        }
    }
}

// ===========================================================================
// GEMM-SMALL v2: 64x128 tile, BK=64, 256 threads (8 warps 2x4, warp 32x32),
// 3-stage, 2 CTAs/SM, grid 6x64 = 384 CTAs (fine-grained load balance).
// fp32 out.
// ===========================================================================
#define GS_ROW   144
#define GS_A     0
#define GS_B     9216                   // A: 64*144
#define GS_STAGE 27648                  // + B: 128*144
#define GS_SMEM  (3*GS_STAGE)

__device__ __forceinline__ void gemm_small_issue(uint32_t sb,
                                                 const __half* Af, const __half* Bf,
                                                 int row0, int col0, int k0, int K, int t) {
    // A: 64 rows x 8 segs = 512 slots -> 2 per thread
    #pragma unroll
    for (int p = 0; p < 2; p++) {
        int id = t + p * 256;
        int r = id >> 3, s = id & 7;
        cp16(sb + GS_A + r * GS_ROW + s * 16, Af + (size_t)(row0 + r) * K + k0 + s * 8);
    }
    // B: 128 rows x 8 segs = 1024 slots -> 4 per thread
    #pragma unroll
    for (int p = 0; p < 4; p++) {
        int id = t + p * 256;
        int r = id >> 3, s = id & 7;
        cp16(sb + GS_B + r * GS_ROW + s * 16, Bf + (size_t)(col0 + r) * K + k0 + s * 8);
    }
}

__global__ __launch_bounds__(256, 2) void gemm_small(const __half* __restrict__ Af,
                                                     const __half* __restrict__ Bf,
                                                     float* __restrict__ Cf,
                                                     int M, int N, int K) {
    extern __shared__ __align__(16) char dyn[];
    const uint32_t sbase = smem_u32(dyn);

    const int t    = threadIdx.x;
    const int lane = t & 31;
    const int wid  = t >> 5;
    const int wm   = (wid >> 2) * 32;   // 2 M groups of 32
    const int wn   = (wid & 3) * 32;    // 4 N groups of 32
    const int row0 = blockIdx.y * 64;
    const int col0 = blockIdx.x * 128;
    const int lrow = lane & 15;
    const int lkof = (lane >> 4) << 3;

    float acc[2][4][4];
    #pragma unroll
    for (int i = 0; i < 2; i++)
        #pragma unroll
        for (int j = 0; j < 4; j++)
            #pragma unroll
            for (int q = 0; q < 4; q++) acc[i][j][q] = 0.f;

    const int nchunk = K / 64;   // 12

    gemm_small_issue(sbase, Af, Bf, row0, col0, 0, K, t);
    CP_COMMIT();
    gemm_small_issue(sbase + GS_STAGE, Af, Bf, row0, col0, 64, K, t);
    CP_COMMIT();

    int stage = 0;
    for (int ch = 0; ch < nchunk; ++ch) {
        if (ch + 1 < nchunk) { CP_WAIT1(); } else { CP_WAIT0(); }
        __syncthreads();
        if (ch + 2 < nchunk) {
            int ns = stage + 2; if (ns >= 3) ns -= 3;
            gemm_small_issue(sbase + ns * GS_STAGE, Af, Bf,
                             row0, col0, (ch + 2) * 64, K, t);
            CP_COMMIT();
        }
        const uint32_t sb = sbase + stage * GS_STAGE;
        if (++stage == 3) stage = 0;

        #pragma unroll
        for (int ks = 0; ks < 4; ks++) {
            const int kb = ks * 16 + lkof;

            uint32_t af[2][4];
            #pragma unroll
            for (int mf = 0; mf < 2; mf++) {
                uint32_t aoff = (uint32_t)((wm + mf * 16 + lrow) * GS_ROW + kb * 2);
                ldm_x4(af[mf], sb + GS_A + aoff);
            }
            {
                uint32_t boff = (uint32_t)((wn + lrow) * GS_ROW + kb * 2);
                uint32_t rb[4];
                ldm_x4(rb, sb + GS_B + boff);
                uint32_t b0[2] = {rb[0], rb[2]};
                uint32_t b1[2] = {rb[1], rb[3]};
                #pragma unroll
                for (int mf = 0; mf < 2; mf++) {
                    mma_f16(acc[mf][0], af[mf], b0);
                    mma_f16(acc[mf][1], af[mf], b1);
                }
            }
            {
                uint32_t boff = (uint32_t)((wn + 16 + lrow) * GS_ROW + kb * 2);
                uint32_t rb[4];
                ldm_x4(rb, sb + GS_B + boff);
                uint32_t b0[2] = {rb[0], rb[2]};
                uint32_t b1[2] = {rb[1], rb[3]};
                #pragma unroll
                for (int mf = 0; mf < 2; mf++) {
                    mma_f16(acc[mf][2], af[mf], b0);
                    mma_f16(acc[mf][3], af[mf], b1);
                }
            }
        }
    }

    #pragma unroll
    for (int mf = 0; mf < 2; mf++) {
        const int row = row0 + wm + mf * 16 + (lane >> 2);
        #pragma unroll
        for (int nf = 0; nf < 4; nf++) {
            const int col = col0 + wn + nf * 8 + (lane & 3) * 2;
            *(float2*)&Cf[(size_t)row * N + col] =
                make_float2(acc[mf][nf][0], acc[mf][nf][1]);
            *(float2*)&Cf[(size_t)(row + 8) * N + col] =
                make_float2(acc[mf][nf][2], acc[mf][nf][3]);
        }
    }
}

// ---------------------------------------------------------------------------
// Flash attention (unchanged R16): 64-query CTAs, 4 warps, 4 CTAs/SM,
// raw-domain max + fused FFMA+exp2, fine-grained causal skip.
// ---------------------------------------------------------------------------
#define A_ROW   144
#define A_K     0
#define A_V     9216
#define A_STAGE 18432
#define A_SMEM  (2*A_STAGE)

__device__ __forceinline__ void attn_issue(uint32_t sb, const __half* qf,
                                           size_t base, int k0, int kcol, int vcol, int t) {
    #pragma unroll
    for (int p = 0; p < 4; p++) {
        int id = t + p * 128;
        int r = id >> 3, s = id & 7;
        size_t gk = base + (size_t)(k0 + r) * QKV_STRIDE + kcol + s * 8;
        size_t gv = base + (size_t)(k0 + r) * QKV_STRIDE + vcol + s * 8;
        uint32_t d = sb + r * A_ROW + s * 16;
        cp16(d + A_K, qf + gk);
        cp16(d + A_V, qf + gv);
    }
}

__global__ __launch_bounds__(128, 4) void attn_mma(const __half* __restrict__ qf16,
                                                   __half* __restrict__ of) {
    extern __shared__ __align__(16) char dyn[];
    const uint32_t sbase = smem_u32(dyn);

    const int t    = threadIdx.x;
    const int lane = t & 31;
    const int w    = t >> 5;
    const int q0   = (gridDim.x - 1 - blockIdx.x) * 64;
    const int h    = blockIdx.y;
    const int b    = blockIdx.z;
    const size_t base = (size_t)b * T_ * QKV_STRIDE;
    const int qcol = h * HD;
    const int kcol = C_ + h * HD;
    const int vcol = 2 * C_ + h * HD;
    const int lrow = lane & 15;
    const int lkof = (lane >> 4) << 3;

    #pragma unroll
    for (int p = 0; p < 4; p++) {
        int id = t + p * 128;
        int r = id >> 3, s = id & 7;
        size_t g = base + (size_t)(q0 + r) * QKV_STRIDE + qcol + s * 8;
        cp16(sbase + A_K + r * A_ROW + s * 16, qf16 + g);
    }
    CP_COMMIT();
    CP_WAIT0();
    __syncthreads();

    uint32_t qf[4][4];
    {
        const uint32_t rofs = (uint32_t)((w * 16 + lrow) * A_ROW);
        #pragma unroll
        for (int ks = 0; ks < 4; ks++) {
            uint32_t co = (uint32_t)((ks * 16 + lkof) * 2);
            ldm_x4(qf[ks], sbase + A_K + rofs + co);
        }
    }
    __syncthreads();

    float mA = -1e30f, mB = -1e30f, lA = 0.f, lB = 0.f;
    float oacc[8][4];
    #pragma unroll
    for (int i = 0; i < 8; i++)
        #pragma unroll
        for (int j = 0; j < 4; j++) oacc[i][j] = 0.f;

    const int rowA = q0 + w * 16 + (lane >> 2);
    const int rowmax = q0 + w * 16 + 15;
    const int ntiles = q0 / 64 + 1;

    attn_issue(sbase, qf16, base, 0, kcol, vcol, t);
    CP_COMMIT();

    for (int kt = 0; kt < ntiles; kt++) {
        const int k0 = kt * 64;
        CP_WAIT0();
        __syncthreads();
        if (kt + 1 < ntiles) {
            attn_issue(sbase + ((kt + 1) & 1) * A_STAGE, qf16, base,
                       (kt + 1) * 64, kcol, vcol, t);
            CP_COMMIT();
        }
        const uint32_t sb = sbase + (kt & 1) * A_STAGE;

        if (k0 <= rowmax) {
            const bool need_mask = (k0 + 63 > q0 + w * 16);

            float sacc[8][4];
            #pragma unroll
            for (int i = 0; i < 8; i++)
                #pragma unroll
                for (int j = 0; j < 4; j++) sacc[i][j] = 0.f;

            #pragma unroll
            for (int ks = 0; ks < 4; ks++) {
                const uint32_t co = (uint32_t)((ks * 16 + lkof) * 2);
                #pragma unroll
                for (int nn = 0; nn < 4; nn++) {
                    if (k0 + nn * 16 <= rowmax) {
                        uint32_t ro = (uint32_t)((nn * 16 + lrow) * A_ROW);
                        uint32_t rh[4];
                        ldm_x4(rh, sb + A_K + ro + co);
                        uint32_t k0f[2] = {rh[0], rh[2]};
                        uint32_t k1f[2] = {rh[1], rh[3]};
                        mma_f16(sacc[2*nn],   qf[ks], k0f);
                        mma_f16(sacc[2*nn+1], qf[ks], k1f);
                    }
                }
            }

            if (need_mask) {
                #pragma unroll
                for (int nf = 0; nf < 8; nf++) {
                    const int col = k0 + nf * 8 + (lane & 3) * 2;
                    if (col     > rowA)     sacc[nf][0] = -1e30f;
                    if (col + 1 > rowA)     sacc[nf][1] = -1e30f;
                    if (col     > rowA + 8) sacc[nf][2] = -1e30f;
                    if (col + 1 > rowA + 8) sacc[nf][3] = -1e30f;
                }
            }

            float tmA = -1e30f, tmB = -1e30f;
            #pragma unroll
            for (int nf = 0; nf < 8; nf++) {
                tmA = fmaxf(tmA, fmaxf(sacc[nf][0], sacc[nf][1]));
                tmB = fmaxf(tmB, fmaxf(sacc[nf][2], sacc[nf][3]));
            }
            tmA = fmaxf(tmA, __shfl_xor_sync(0xffffffffu, tmA, 1));
            tmA = fmaxf(tmA, __shfl_xor_sync(0xffffffffu, tmA, 2));
            tmB = fmaxf(tmB, __shfl_xor_sync(0xffffffffu, tmB, 1));
            tmB = fmaxf(tmB, __shfl_xor_sync(0xffffffffu, tmB, 2));

            const float mnA = fmaxf(mA, tmA);
            const float mnB = fmaxf(mB, tmB);
            const float aA = exp2f((mA - mnA) * SCL2);
            const float aB = exp2f((mB - mnB) * SCL2);
            const float cA = mnA * SCL2;
            const float cB = mnB * SCL2;

            float sumA = 0.f, sumB = 0.f;
            #pragma unroll
            for (int nf = 0; nf < 8; nf++) {
                sacc[nf][0] = exp2f(fmaf(sacc[nf][0], SCL2, -cA));
                sacc[nf][1] = exp2f(fmaf(sacc[nf][1], SCL2, -cA));
                sacc[nf][2] = exp2f(fmaf(sacc[nf][2], SCL2, -cB));
                sacc[nf][3] = exp2f(fmaf(sacc[nf][3], SCL2, -cB));
                sumA += sacc[nf][0] + sacc[nf][1];
                sumB += sacc[nf][2] + sacc[nf][3];
            }
            sumA += __shfl_xor_sync(0xffffffffu, sumA, 1);
            sumA += __shfl_xor_sync(0xffffffffu, sumA, 2);
            sumB += __shfl_xor_sync(0xffffffffu, sumB, 1);
            sumB += __shfl_xor_sync(0xffffffffu, sumB, 2);

            lA = lA * aA + sumA;  mA = mnA;
            lB = lB * aB + sumB;  mB = mnB;

            #pragma unroll
            for (int nf = 0; nf < 8; nf++) {
                oacc[nf][0] *= aA; oacc[nf][1] *= aA;
                oacc[nf][2] *= aB; oacc[nf][3] *= aB;
            }

            #pragma unroll
            for (int ks = 0; ks < 4; ks++) {
                if (k0 + ks * 16 <= rowmax) {
                    uint32_t ph[4];
                    ph[0] = pack_h2(sacc[2*ks][0],   sacc[2*ks][1]);
                    ph[1] = pack_h2(sacc[2*ks][2],   sacc[2*ks][3]);
                    ph[2] = pack_h2(sacc[2*ks+1][0], sacc[2*ks+1][1]);
                    ph[3] = pack_h2(sacc[2*ks+1][2], sacc[2*ks+1][3]);

                    const uint32_t krofs = (uint32_t)((ks * 16 + lrow) * A_ROW);
                    #pragma unroll
                    for (int nn = 0; nn < 4; nn++) {
                        uint32_t co = (uint32_t)((nn * 16 + lkof) * 2);
                        uint32_t vf[4];
                        ldm_x4_t(vf, sb + A_V + krofs + co);
                        uint32_t b0[2] = {vf[0], vf[1]};
                        uint32_t b1[2] = {vf[2], vf[3]};
                        mma_f16(oacc[2*nn],   ph, b0);
                        mma_f16(oacc[2*nn+1], ph, b1);
                    }
                }
            }
        }
    }

    const float invA = 1.f / lA;
    const float invB = 1.f / lB;
    const size_t orowA = ((size_t)b * T_ + rowA) * C_ + h * HD;
    #pragma unroll
    for (int nf = 0; nf < 8; nf++) {
        const int col = nf * 8 + (lane & 3) * 2;
        #pragma unroll
        for (int half_ = 0; half_ < 2; half_++) {
            const size_t o = orowA + half_ * 8 * C_ + col;
            __half2 hv = __floats2half2_rn(oacc[nf][2*half_]     * (half_ ? invB : invA),
                                           oacc[nf][2*half_ + 1] * (half_ ? invB : invA));
            *(__half2*)&of[o] = hv;
        }
    }
}

// ===========================================================================
extern "C" void kernel_launch(void* const* d_in, const int* in_sizes, int n_in,
                              void* d_out, int out_size) {
    const float* x      = (const float*)d_in[0];   // [B,T,C]
    const float* W_attn = (const float*)d_in[1];   // [3C,C]
    const float* W_proj = (const float*)d_in[2];   // [C,C]
    float* out = (float*)d_out;                    // [B,T,C]

    __half *xf, *wa, *wp, *qf, *af;
    cudaGetSymbolAddress((void**)&xf, g_xf);
    cudaGetSymbolAddress((void**)&wa, g_wa); cudaGetSymbolAddress((void**)&wp, g_wp);
    cudaGetSymbolAddress((void**)&qf, g_qf);
    cudaGetSymbolAddress((void**)&af, g_af);

    cudaFuncSetAttribute(gemm_big,   cudaFuncAttributeMaxDynamicSharedMemorySize, GB_SMEM);
    cudaFuncSetAttribute(gemm_small, cudaFuncAttributeMaxDynamicSharedMemorySize, GS_SMEM);
    cudaFuncSetAttribute(attn_mma,   cudaFuncAttributeMaxDynamicSharedMemorySize, A_SMEM);

    // 0) conversions (single launch)
    conv_all<<<(N4_TOT + 255) / 256, 256>>>(x, W_attn, W_proj, xf, wa, wp);

    // 1) qkv = x @ W_attn^T  -> fp16   [4096 x 2304]
    gemm_big<<<dim3((3*C_)/256, M_/128), 512, GB_SMEM>>>(xf, wa, qf, M_, 3*C_, C_);

    // 2) causal attention (fp16) -> fp16   (64-query CTAs, 4/SM)
    attn_mma<<<dim3(T_/64, NH, B_), 128, A_SMEM>>>(qf, af);

    // 3) out = attn @ W_proj^T -> fp32   [4096 x 768], 384 CTAs (64x128 tiles)
    gemm_small<<<dim3(C_/128, M_/64), 256, GS_SMEM>>>(af, wp, out, M_, C_, C_);
}